// round 1
// baseline (speedup 1.0000x reference)
#include <cuda_runtime.h>

// ---------------------------------------------------------------------------
// UFOAttention restructured:
//   M[b,h]  = sum_l outer(k_raw[b,l,h,:], v_raw[b,l,h,:])          (kernel 1)
//   kv      = Wk M Wv^T ; kv_n = xnorm(kv) ; P = Wq^T kv_n ;
//   G[b,h]  = P * Wo_h^T  (64x512)                                  (kernel 2)
//   s[b,l,h]= gamma_h / ||q_raw[b,l,h,:] Wq^T||_4                   (kernel 3)
//   out[b,l,:] = bo + sum_h s[b,l,h] * q_raw[b,l,h,:] * G[b,h]      (kernel 4)
// No k/v projections, no per-head output, no concat intermediate.
// ---------------------------------------------------------------------------

constexpr int CB = 8;      // batch
constexpr int CL = 8192;   // seq len
constexpr int CH = 8;      // heads
constexpr int CD = 64;     // head dim
constexpr int CE = 512;    // embed
constexpr int NCH = 8;     // L-chunks for M partials
constexpr int CHUNK = CL / NCH;

__device__ float g_Mpart[CB * CH * NCH * CD * CD]; // 8 MB partial moments
__device__ float g_G[CB * CH * CD * CE];           // 8 MB folded matrices
__device__ float g_S[CB * CL * CH];                // 2 MB per-row scales

typedef unsigned long long u64;

__device__ __forceinline__ u64 pack2(float a, float b) {
    u64 r; asm("mov.b64 %0, {%1,%2};" : "=l"(r) : "f"(a), "f"(b)); return r;
}
__device__ __forceinline__ void unpack2(u64 v, float& a, float& b) {
    asm("mov.b64 {%0,%1}, %2;" : "=f"(a), "=f"(b) : "l"(v));
}
__device__ __forceinline__ u64 fma2(u64 a, u64 b, u64 c) {
    u64 d; asm("fma.rn.f32x2 %0, %1, %2, %3;" : "=l"(d) : "l"(a), "l"(b), "l"(c)); return d;
}

// ---------------------------------------------------------------------------
// Kernel 1: raw moment matrices M[i,j] = sum_l k[l,i] * v[l,j], per (b,h).
// Grid: B*H*NCH blocks x 256 threads. Each thread owns a 4x4 tile of M.
// Deterministic: partials written per chunk, summed in kernel 2.
// ---------------------------------------------------------------------------
__global__ __launch_bounds__(256) void k1_moment(const float* __restrict__ keys,
                                                 const float* __restrict__ values) {
    int blk = blockIdx.x;
    int chunk = blk % NCH;
    int bh = blk / NCH;
    int h = bh % CH, b = bh / CH;
    int t = threadIdx.x;
    int ti = t >> 4, tj = t & 15;
    int lo = t >> 6, dd = t & 63;

    __shared__ float sk[4][64], sv[4][64];

    u64 acc[4][2];
#pragma unroll
    for (int r = 0; r < 4; r++) { acc[r][0] = 0ull; acc[r][1] = 0ull; }

    const float* kb = keys   + ((size_t)b * CL) * CE + h * CD;
    const float* vb = values + ((size_t)b * CL) * CE + h * CD;
    int l0 = chunk * CHUNK;

    for (int l = l0; l < l0 + CHUNK; l += 4) {
        __syncthreads();
        size_t roff = (size_t)(l + lo) * CE + dd;
        sk[lo][dd] = kb[roff];
        sv[lo][dd] = vb[roff];
        __syncthreads();
#pragma unroll
        for (int ll = 0; ll < 4; ll++) {
            u64 kk[4];
#pragma unroll
            for (int r = 0; r < 4; r++) { float kv_ = sk[ll][4 * ti + r]; kk[r] = pack2(kv_, kv_); }
            u64 v0 = *(const u64*)&sv[ll][4 * tj];
            u64 v1 = *(const u64*)&sv[ll][4 * tj + 2];
#pragma unroll
            for (int r = 0; r < 4; r++) {
                acc[r][0] = fma2(kk[r], v0, acc[r][0]);
                acc[r][1] = fma2(kk[r], v1, acc[r][1]);
            }
        }
    }

    float* Mp = g_Mpart + ((size_t)bh * NCH + chunk) * (CD * CD);
#pragma unroll
    for (int r = 0; r < 4; r++) {
        float a, bv, c, dv;
        unpack2(acc[r][0], a, bv);
        unpack2(acc[r][1], c, dv);
        int row = 4 * ti + r;
        Mp[row * 64 + 4 * tj + 0] = a;
        Mp[row * 64 + 4 * tj + 1] = bv;
        Mp[row * 64 + 4 * tj + 2] = c;
        Mp[row * 64 + 4 * tj + 3] = dv;
    }
}

// ---------------------------------------------------------------------------
// Kernel 2: per (b,h): kv = Wk M Wv^T; xnorm rows; P = Wq^T kv_n; G = P Wo_h^T.
// Grid: 64 blocks x 256 threads. Each thread owns a 4x4 tile per stage.
// ---------------------------------------------------------------------------
__global__ __launch_bounds__(256) void k2_prepG(const float* __restrict__ Wq,
                                                const float* __restrict__ Wk,
                                                const float* __restrict__ Wv,
                                                const float* __restrict__ Wo,
                                                const float* __restrict__ gamma) {
    __shared__ float sA[4096];
    __shared__ float sB[4096];
    __shared__ float rs[64];

    int bh = blockIdx.x;
    int h = bh & 7;
    int t = threadIdx.x;
    int i0 = (t >> 4) * 4, j0 = (t & 15) * 4;

    // Load summed M into sA, Wv into sB.
    for (int idx = t; idx < 4096; idx += 256) {
        float s = 0.f;
#pragma unroll
        for (int c = 0; c < NCH; c++) s += g_Mpart[((size_t)bh * NCH + c) * 4096 + idx];
        sA[idx] = s;
        sB[idx] = Wv[idx];
    }
    __syncthreads();

    float r16[4][4];

    // Stage 1: T[i,e] = sum_j M[i,j] Wv[e,j]
#pragma unroll
    for (int r = 0; r < 4; r++)
#pragma unroll
        for (int c = 0; c < 4; c++) r16[r][c] = 0.f;
    for (int j = 0; j < 64; j++) {
        float a[4], bv[4];
#pragma unroll
        for (int r = 0; r < 4; r++) a[r] = sA[(i0 + r) * 64 + j];
#pragma unroll
        for (int c = 0; c < 4; c++) bv[c] = sB[(j0 + c) * 64 + j];
#pragma unroll
        for (int r = 0; r < 4; r++)
#pragma unroll
            for (int c = 0; c < 4; c++) r16[r][c] += a[r] * bv[c];
    }
    __syncthreads();
#pragma unroll
    for (int r = 0; r < 4; r++)
#pragma unroll
        for (int c = 0; c < 4; c++) sA[(i0 + r) * 64 + j0 + c] = r16[r][c];
    for (int idx = t; idx < 4096; idx += 256) sB[idx] = Wk[idx];
    __syncthreads();

    // Stage 2: kv[d,e] = sum_i Wk[d,i] T[i,e]
#pragma unroll
    for (int r = 0; r < 4; r++)
#pragma unroll
        for (int c = 0; c < 4; c++) r16[r][c] = 0.f;
    for (int i = 0; i < 64; i++) {
        float a[4], bv[4];
#pragma unroll
        for (int r = 0; r < 4; r++) a[r] = sB[(i0 + r) * 64 + i];
#pragma unroll
        for (int c = 0; c < 4; c++) bv[c] = sA[i * 64 + j0 + c];
#pragma unroll
        for (int r = 0; r < 4; r++)
#pragma unroll
            for (int c = 0; c < 4; c++) r16[r][c] += a[r] * bv[c];
    }
    __syncthreads();
#pragma unroll
    for (int r = 0; r < 4; r++)
#pragma unroll
        for (int c = 0; c < 4; c++) sA[(i0 + r) * 64 + j0 + c] = r16[r][c];
    for (int idx = t; idx < 4096; idx += 256) sB[idx] = Wq[idx];
    __syncthreads();

    // Stage 3: per-row L4 norm scale: rs[d] = gamma_h * (sum_e kv^4)^(-1/4)
    {
        int w = t >> 5, lane = t & 31;
        float g = gamma[h];
        for (int d = w * 8; d < w * 8 + 8; d++) {
            float x1 = sA[d * 64 + lane], x2 = sA[d * 64 + lane + 32];
            float p = (x1 * x1) * (x1 * x1) + (x2 * x2) * (x2 * x2);
#pragma unroll
            for (int o = 16; o > 0; o >>= 1) p += __shfl_xor_sync(0xffffffffu, p, o);
            if (lane == 0) rs[d] = g * rsqrtf(sqrtf(p));
        }
    }
    __syncthreads();
    for (int idx = t; idx < 4096; idx += 256) sA[idx] *= rs[idx >> 6];
    __syncthreads();

    // Stage 4: P[i,e] = sum_d Wq[d,i] kv_n[d,e]
#pragma unroll
    for (int r = 0; r < 4; r++)
#pragma unroll
        for (int c = 0; c < 4; c++) r16[r][c] = 0.f;
    for (int d = 0; d < 64; d++) {
        float a[4], bv[4];
#pragma unroll
        for (int r = 0; r < 4; r++) a[r] = sB[d * 64 + i0 + r];
#pragma unroll
        for (int c = 0; c < 4; c++) bv[c] = sA[d * 64 + j0 + c];
#pragma unroll
        for (int r = 0; r < 4; r++)
#pragma unroll
            for (int c = 0; c < 4; c++) r16[r][c] += a[r] * bv[c];
    }
    __syncthreads();
#pragma unroll
    for (int r = 0; r < 4; r++)
#pragma unroll
        for (int c = 0; c < 4; c++) sA[(i0 + r) * 64 + j0 + c] = r16[r][c];
    __syncthreads();

    // Stage 5: G[i,f] = sum_e P[i,e] Wo[f, h*64+e], written tile-by-tile over f.
    float* Gp = g_G + (size_t)bh * CD * CE;
    for (int fb = 0; fb < 8; fb++) {
        for (int idx = t; idx < 4096; idx += 256) {
            int ff = idx >> 6, e = idx & 63;
            sB[idx] = Wo[(size_t)(fb * 64 + ff) * 512 + h * 64 + e];
        }
        __syncthreads();
#pragma unroll
        for (int r = 0; r < 4; r++)
#pragma unroll
            for (int c = 0; c < 4; c++) r16[r][c] = 0.f;
        for (int e = 0; e < 64; e++) {
            float a[4], bv[4];
#pragma unroll
            for (int r = 0; r < 4; r++) a[r] = sA[(i0 + r) * 64 + e];
#pragma unroll
            for (int c = 0; c < 4; c++) bv[c] = sB[(j0 + c) * 64 + e];
#pragma unroll
            for (int r = 0; r < 4; r++)
#pragma unroll
                for (int c = 0; c < 4; c++) r16[r][c] += a[r] * bv[c];
        }
#pragma unroll
        for (int r = 0; r < 4; r++)
#pragma unroll
            for (int c = 0; c < 4; c++)
                Gp[(size_t)(i0 + r) * 512 + fb * 64 + j0 + c] = r16[r][c];
        __syncthreads();
    }
}

// ---------------------------------------------------------------------------
// Kernel 3: s[b,l,h] = gamma_h * (sum_e (q_raw[l,h,:] . Wq[e,:])^4)^(-1/4).
// Grid: B*L/8 blocks x 256 threads (8 warps; 16 (head,row-group) tasks).
// ---------------------------------------------------------------------------
__global__ __launch_bounds__(256) void k3_scales(const float* __restrict__ queries,
                                                 const float* __restrict__ Wq,
                                                 const float* __restrict__ gamma) {
    __shared__ float sWqt[4096];  // transposed: sWqt[d*64+e] = Wq[e,d]
    __shared__ float sq[8 * 512];
    __shared__ float sg[8];

    int t = threadIdx.x;
    size_t R0 = (size_t)blockIdx.x * 8;

    for (int idx = t; idx < 4096; idx += 256) {
        int e = idx >> 6, d = idx & 63;
        sWqt[d * 64 + e] = Wq[idx];
    }
    for (int idx = t; idx < 4096; idx += 256) sq[idx] = queries[R0 * 512 + idx];
    if (t < 8) sg[t] = gamma[t];
    __syncthreads();

    int w = t >> 5, lane = t & 31;
    for (int task = w; task < 16; task += 8) {
        int h = task & 7, rg = task >> 3;
        u64 acc[4] = {0ull, 0ull, 0ull, 0ull};
        for (int d = 0; d < 64; d++) {
            u64 w2 = *(const u64*)&sWqt[d * 64 + 2 * lane];
#pragma unroll
            for (int rr = 0; rr < 4; rr++) {
                float qv = sq[(rg * 4 + rr) * 512 + h * 64 + d];
                acc[rr] = fma2(pack2(qv, qv), w2, acc[rr]);
            }
        }
#pragma unroll
        for (int rr = 0; rr < 4; rr++) {
            float a, bv;
            unpack2(acc[rr], a, bv);
            float p = (a * a) * (a * a) + (bv * bv) * (bv * bv);
#pragma unroll
            for (int o = 16; o > 0; o >>= 1) p += __shfl_xor_sync(0xffffffffu, p, o);
            if (lane == 0) g_S[(R0 + rg * 4 + rr) * CH + h] = sg[h] * rsqrtf(sqrtf(p));
        }
    }
}

// ---------------------------------------------------------------------------
// Kernel 4: out[b,l,f] = bo[f] + sum_k (s[l,k/64]*q_raw[l,k]) * G[b][k,f].
// Tiled 128x128x16 fp32 GEMM with packed f32x2 FMA. Grid (4, 64, 8) x 256.
// ---------------------------------------------------------------------------
__global__ __launch_bounds__(256) void k4_gemm(const float* __restrict__ queries,
                                               const float* __restrict__ bo,
                                               float* __restrict__ out) {
    __shared__ float As[16][128];
    __shared__ float Bs[16][128];

    int b = blockIdx.z, mt = blockIdx.y, nt = blockIdx.x;
    int t = threadIdx.x;
    int tx = t & 15, ty = t >> 4;
    int m0 = ty * 8, n0 = tx * 8;

    size_t rowbase = (size_t)b * CL + (size_t)mt * 128;
    const float* qbase = queries + rowbase * 512;

    int lr = t >> 1;
    int kq = (t & 1) * 8;
    int bkk = t >> 4;
    int bf = (t & 15) * 8;

    u64 acc[4][8];
#pragma unroll
    for (int p = 0; p < 4; p++)
#pragma unroll
        for (int j = 0; j < 8; j++) acc[p][j] = 0ull;

    for (int kt = 0; kt < 32; kt++) {
        int h = kt >> 2;
        float s = g_S[(rowbase + lr) * CH + h];
        const float* arow = qbase + (size_t)lr * 512 + kt * 16 + kq;
        float4 a0 = *(const float4*)(arow);
        float4 a1 = *(const float4*)(arow + 4);
        int i = (kt & 3) * 16 + bkk;
        const float* grow = g_G + (((size_t)(b * CH + h)) * 64 + i) * 512 + nt * 128 + bf;
        float4 b0 = *(const float4*)(grow);
        float4 b1 = *(const float4*)(grow + 4);

        __syncthreads();
        As[kq + 0][lr] = s * a0.x; As[kq + 1][lr] = s * a0.y;
        As[kq + 2][lr] = s * a0.z; As[kq + 3][lr] = s * a0.w;
        As[kq + 4][lr] = s * a1.x; As[kq + 5][lr] = s * a1.y;
        As[kq + 6][lr] = s * a1.z; As[kq + 7][lr] = s * a1.w;
        *(float4*)&Bs[bkk][bf] = b0;
        *(float4*)&Bs[bkk][bf + 4] = b1;
        __syncthreads();

#pragma unroll
        for (int kk = 0; kk < 16; kk++) {
            u64 a2[4];
#pragma unroll
            for (int p = 0; p < 4; p++) a2[p] = *(const u64*)&As[kk][m0 + 2 * p];
            float bv[8];
#pragma unroll
            for (int j = 0; j < 8; j++) bv[j] = Bs[kk][n0 + j];
#pragma unroll
            for (int j = 0; j < 8; j++) {
                u64 bd = pack2(bv[j], bv[j]);
#pragma unroll
                for (int p = 0; p < 4; p++) acc[p][j] = fma2(a2[p], bd, acc[p][j]);
            }
        }
    }

    float bv[8];
#pragma unroll
    for (int j = 0; j < 8; j++) bv[j] = bo[nt * 128 + n0 + j];
#pragma unroll
    for (int p = 0; p < 4; p++) {
        size_t r0 = rowbase + m0 + 2 * p;
#pragma unroll
        for (int j = 0; j < 8; j++) {
            float lo2, hi2;
            unpack2(acc[p][j], lo2, hi2);
            out[r0 * 512 + nt * 128 + n0 + j] = lo2 + bv[j];
            out[(r0 + 1) * 512 + nt * 128 + n0 + j] = hi2 + bv[j];
        }
    }
}

// ---------------------------------------------------------------------------
extern "C" void kernel_launch(void* const* d_in, const int* in_sizes, int n_in,
                              void* d_out, int out_size) {
    const float* queries = (const float*)d_in[0];
    const float* keys    = (const float*)d_in[1];
    const float* values  = (const float*)d_in[2];
    const float* Wq      = (const float*)d_in[3];
    const float* Wk      = (const float*)d_in[4];
    const float* Wv      = (const float*)d_in[5];
    const float* Wo      = (const float*)d_in[6];
    const float* bo      = (const float*)d_in[7];
    const float* gamma   = (const float*)d_in[8];
    float* out = (float*)d_out;

    k1_moment<<<CB * CH * NCH, 256>>>(keys, values);
    k2_prepG<<<CB * CH, 256>>>(Wq, Wk, Wv, Wo, gamma);
    k3_scales<<<CB * CL / 8, 256>>>(queries, Wq, gamma);
    k4_gemm<<<dim3(4, CL / 128, CB), 256>>>(queries, bo, out);
}

// round 8
// speedup vs baseline: 1.3948x; 1.3948x over previous
#include <cuda_runtime.h>
#include <cuda_bf16.h>
#include <cstdint>

// ---------------------------------------------------------------------------
// UFOAttention restructured:
//   M[b,h]  = sum_l outer(k_raw[b,l,h,:], v_raw[b,l,h,:])            (k1)
//   kv = Wk M Wv^T ; kv_n = xnorm ; P = Wq^T kv_n ; G = P Wo_h^T ;
//   Gt (transposed, split to bf16 hi/lo)                              (k2)
//   s[b,l,h] = gamma_h / ||q_raw[b,l,h,:] Wq^T||_4                    (k3)
//   out[b]  = diag(s)*Q_raw @ Gbig + bo  via mma.sync bf16 3-pass     (k4)
// Plain sm_103-legal instructions only (no tcgen05 — target lacks 'a').
// ---------------------------------------------------------------------------

constexpr int CB = 8;
constexpr int CL = 8192;
constexpr int CH = 8;
constexpr int CD = 64;
constexpr int CE = 512;
constexpr int NCH = 16;
constexpr int CHUNK = CL / NCH;   // 512

__device__ float g_Mpart[CB * CH * NCH * CD * CD];
__device__ float g_S[CB * CL * CH];
__device__ __nv_bfloat16 g_Gt_hi[CB * CE * CE];   // [b][f][k]
__device__ __nv_bfloat16 g_Gt_lo[CB * CE * CE];

typedef unsigned long long u64;

__device__ __forceinline__ u64 pack2(float a, float b) {
    u64 r; asm("mov.b64 %0, {%1,%2};" : "=l"(r) : "f"(a), "f"(b)); return r;
}
__device__ __forceinline__ void unpack2(u64 v, float& a, float& b) {
    asm("mov.b64 {%0,%1}, %2;" : "=f"(a), "=f"(b) : "l"(v));
}
__device__ __forceinline__ u64 fma2(u64 a, u64 b, u64 c) {
    u64 d; asm("fma.rn.f32x2 %0, %1, %2, %3;" : "=l"(d) : "l"(a), "l"(b), "l"(c)); return d;
}
__device__ __forceinline__ uint32_t smem_u32(const void* p) {
    uint32_t a;
    asm("{ .reg .u64 t; cvta.to.shared.u64 t, %1; cvt.u32.u64 %0, t; }" : "=r"(a) : "l"(p));
    return a;
}
#define CP_COMMIT() asm volatile("cp.async.commit_group;" ::: "memory")
#define CP_WAIT(n)  asm volatile("cp.async.wait_group %0;" :: "n"(n) : "memory")
__device__ __forceinline__ void cp16(uint32_t dst, const void* src) {
    asm volatile("cp.async.ca.shared.global [%0], [%1], 16;" :: "r"(dst), "l"(src) : "memory");
}
__device__ __forceinline__ void ldsm4(uint32_t* r, uint32_t a) {
    asm volatile("ldmatrix.sync.aligned.m8n8.x4.shared.b16 {%0,%1,%2,%3}, [%4];"
                 : "=r"(r[0]), "=r"(r[1]), "=r"(r[2]), "=r"(r[3]) : "r"(a));
}
__device__ __forceinline__ void mma16816(float* c, const uint32_t* a, const uint32_t* b) {
    asm volatile("mma.sync.aligned.m16n8k16.row.col.f32.bf16.bf16.f32 "
                 "{%0,%1,%2,%3}, {%4,%5,%6,%7}, {%8,%9}, {%0,%1,%2,%3};"
                 : "+f"(c[0]), "+f"(c[1]), "+f"(c[2]), "+f"(c[3])
                 : "r"(a[0]), "r"(a[1]), "r"(a[2]), "r"(a[3]), "r"(b[0]), "r"(b[1]));
}
__device__ __forceinline__ uint32_t pack_bf(__nv_bfloat16 a, __nv_bfloat16 b) {
    unsigned short x = *(unsigned short*)&a, y = *(unsigned short*)&b;
    return (uint32_t)x | ((uint32_t)y << 16);
}

// ---------------------------------------------------------------------------
// Kernel 1: partial raw moments, 3-stage cp.async pipeline, 16 rows/stage.
// ---------------------------------------------------------------------------
__global__ __launch_bounds__(256) void k1_moment(const float* __restrict__ keys,
                                                 const float* __restrict__ values) {
    constexpr int RS = 16;
    constexpr int NIT = CHUNK / RS;   // 32
    __shared__ __align__(16) float sk[3][RS][64];
    __shared__ __align__(16) float sv[3][RS][64];

    int blk = blockIdx.x;
    int chunk = blk % NCH;
    int bh = blk / NCH;
    int hh = bh % CH, b = bh / CH;
    int t = threadIdx.x;
    int ti = t >> 4, tj = t & 15;
    int crow = t >> 4, cc = t & 15;     // copy role: row, 16B chunk

    const float* kb = keys   + (size_t)b * CL * CE + hh * CD;
    const float* vb = values + (size_t)b * CL * CE + hh * CD;
    int l0 = chunk * CHUNK;

    u64 acc[4][2];
#pragma unroll
    for (int r = 0; r < 4; r++) { acc[r][0] = 0ull; acc[r][1] = 0ull; }

    // prologue: stages 0,1
#pragma unroll
    for (int pit = 0; pit < 2; pit++) {
        size_t l = (size_t)(l0 + pit * RS + crow);
        cp16(smem_u32(&sk[pit][crow][cc * 4]), kb + l * CE + cc * 4);
        cp16(smem_u32(&sv[pit][crow][cc * 4]), vb + l * CE + cc * 4);
        CP_COMMIT();
    }

    for (int it = 0; it < NIT; it++) {
        int s = it % 3;
        if (it < NIT - 1) CP_WAIT(1); else CP_WAIT(0);
        __syncthreads();
        if (it + 2 < NIT) {
            int ns = (it + 2) % 3;
            size_t l = (size_t)(l0 + (it + 2) * RS + crow);
            cp16(smem_u32(&sk[ns][crow][cc * 4]), kb + l * CE + cc * 4);
            cp16(smem_u32(&sv[ns][crow][cc * 4]), vb + l * CE + cc * 4);
            CP_COMMIT();
        }
#pragma unroll
        for (int r = 0; r < RS; r++) {
            u64 kk[4];
#pragma unroll
            for (int rr = 0; rr < 4; rr++) {
                float kv_ = sk[s][r][4 * ti + rr];
                kk[rr] = pack2(kv_, kv_);
            }
            u64 v0 = *(const u64*)&sv[s][r][4 * tj];
            u64 v1 = *(const u64*)&sv[s][r][4 * tj + 2];
#pragma unroll
            for (int rr = 0; rr < 4; rr++) {
                acc[rr][0] = fma2(kk[rr], v0, acc[rr][0]);
                acc[rr][1] = fma2(kk[rr], v1, acc[rr][1]);
            }
        }
    }

    float* Mp = g_Mpart + ((size_t)bh * NCH + chunk) * (CD * CD);
#pragma unroll
    for (int r = 0; r < 4; r++) {
        float a, bv, c, dv;
        unpack2(acc[r][0], a, bv);
        unpack2(acc[r][1], c, dv);
        int row = 4 * ti + r;
        Mp[row * 64 + 4 * tj + 0] = a;
        Mp[row * 64 + 4 * tj + 1] = bv;
        Mp[row * 64 + 4 * tj + 2] = c;
        Mp[row * 64 + 4 * tj + 3] = dv;
    }
}

// ---------------------------------------------------------------------------
// Kernel 2: per (b,h) G = Wq^T xnorm(Wk M Wv^T) Wo_h^T -> Gt hi/lo bf16.
// ---------------------------------------------------------------------------
__global__ __launch_bounds__(256) void k2_prepG(const float* __restrict__ Wq,
                                                const float* __restrict__ Wk,
                                                const float* __restrict__ Wv,
                                                const float* __restrict__ Wo,
                                                const float* __restrict__ gamma) {
    __shared__ float sA[4096];
    __shared__ float sB[4096];
    __shared__ float rs[64];

    int bh = blockIdx.x;
    int hh = bh & 7, b = bh >> 3;
    int t = threadIdx.x;
    int i0 = (t >> 4) * 4, j0 = (t & 15) * 4;

    for (int idx = t; idx < 4096; idx += 256) {
        float s = 0.f;
#pragma unroll
        for (int c = 0; c < NCH; c++) s += g_Mpart[((size_t)bh * NCH + c) * 4096 + idx];
        sA[idx] = s;
        sB[idx] = Wv[idx];
    }
    __syncthreads();

    float r16[4][4];

    // Stage 1: T[i,e] = sum_j M[i,j] Wv[e,j]
#pragma unroll
    for (int r = 0; r < 4; r++)
#pragma unroll
        for (int c = 0; c < 4; c++) r16[r][c] = 0.f;
    for (int j = 0; j < 64; j++) {
        float a[4], bv[4];
#pragma unroll
        for (int r = 0; r < 4; r++) a[r] = sA[(i0 + r) * 64 + j];
#pragma unroll
        for (int c = 0; c < 4; c++) bv[c] = sB[(j0 + c) * 64 + j];
#pragma unroll
        for (int r = 0; r < 4; r++)
#pragma unroll
            for (int c = 0; c < 4; c++) r16[r][c] += a[r] * bv[c];
    }
    __syncthreads();
#pragma unroll
    for (int r = 0; r < 4; r++)
#pragma unroll
        for (int c = 0; c < 4; c++) sA[(i0 + r) * 64 + j0 + c] = r16[r][c];
    for (int idx = t; idx < 4096; idx += 256) sB[idx] = Wk[idx];
    __syncthreads();

    // Stage 2: kv[d,e] = sum_i Wk[d,i] T[i,e]
#pragma unroll
    for (int r = 0; r < 4; r++)
#pragma unroll
        for (int c = 0; c < 4; c++) r16[r][c] = 0.f;
    for (int i = 0; i < 64; i++) {
        float a[4], bv[4];
#pragma unroll
        for (int r = 0; r < 4; r++) a[r] = sB[(i0 + r) * 64 + i];
#pragma unroll
        for (int c = 0; c < 4; c++) bv[c] = sA[i * 64 + j0 + c];
#pragma unroll
        for (int r = 0; r < 4; r++)
#pragma unroll
            for (int c = 0; c < 4; c++) r16[r][c] += a[r] * bv[c];
    }
    __syncthreads();
#pragma unroll
    for (int r = 0; r < 4; r++)
#pragma unroll
        for (int c = 0; c < 4; c++) sA[(i0 + r) * 64 + j0 + c] = r16[r][c];
    for (int idx = t; idx < 4096; idx += 256) sB[idx] = Wq[idx];
    __syncthreads();

    // Stage 3: rs[d] = gamma_h * (sum_e kv[d,e]^4)^(-1/4)
    {
        int w = t >> 5, lane = t & 31;
        float g = gamma[hh];
        for (int d = w * 8; d < w * 8 + 8; d++) {
            float x1 = sA[d * 64 + lane], x2 = sA[d * 64 + lane + 32];
            float p = (x1 * x1) * (x1 * x1) + (x2 * x2) * (x2 * x2);
#pragma unroll
            for (int o = 16; o > 0; o >>= 1) p += __shfl_xor_sync(0xffffffffu, p, o);
            if (lane == 0) rs[d] = g * rsqrtf(sqrtf(p));
        }
    }
    __syncthreads();
    for (int idx = t; idx < 4096; idx += 256) sA[idx] *= rs[idx >> 6];
    __syncthreads();

    // Stage 4: P[i,e] = sum_d Wq[d,i] kv_n[d,e]
#pragma unroll
    for (int r = 0; r < 4; r++)
#pragma unroll
        for (int c = 0; c < 4; c++) r16[r][c] = 0.f;
    for (int d = 0; d < 64; d++) {
        float a[4], bv[4];
#pragma unroll
        for (int r = 0; r < 4; r++) a[r] = sB[d * 64 + i0 + r];
#pragma unroll
        for (int c = 0; c < 4; c++) bv[c] = sA[d * 64 + j0 + c];
#pragma unroll
        for (int r = 0; r < 4; r++)
#pragma unroll
            for (int c = 0; c < 4; c++) r16[r][c] += a[r] * bv[c];
    }
    __syncthreads();
#pragma unroll
    for (int r = 0; r < 4; r++)
#pragma unroll
        for (int c = 0; c < 4; c++) sA[(i0 + r) * 64 + j0 + c] = r16[r][c];
    __syncthreads();

    // Stage 5: G[i,f] = sum_e P[i,e] Wo[f, h*64+e] -> Gt hi/lo
    for (int fb = 0; fb < 8; fb++) {
        for (int idx = t; idx < 4096; idx += 256) {
            int ff = idx >> 6, e = idx & 63;
            sB[idx] = Wo[(size_t)(fb * 64 + ff) * 512 + hh * 64 + e];
        }
        __syncthreads();
#pragma unroll
        for (int r = 0; r < 4; r++)
#pragma unroll
            for (int c = 0; c < 4; c++) r16[r][c] = 0.f;
        for (int e = 0; e < 64; e++) {
            float a[4], bv[4];
#pragma unroll
            for (int r = 0; r < 4; r++) a[r] = sA[(i0 + r) * 64 + e];
#pragma unroll
            for (int c = 0; c < 4; c++) bv[c] = sB[(j0 + c) * 64 + e];
#pragma unroll
            for (int r = 0; r < 4; r++)
#pragma unroll
                for (int c = 0; c < 4; c++) r16[r][c] += a[r] * bv[c];
        }
#pragma unroll
        for (int r = 0; r < 4; r++)
#pragma unroll
            for (int c = 0; c < 4; c++) {
                float val = r16[r][c];
                __nv_bfloat16 vh = __float2bfloat16(val);
                __nv_bfloat16 vl = __float2bfloat16(val - __bfloat162float(vh));
                size_t p = ((size_t)b * 512 + fb * 64 + j0 + c) * 512 + hh * 64 + i0 + r;
                g_Gt_hi[p] = vh;
                g_Gt_lo[p] = vl;
            }
        __syncthreads();
    }
}

// ---------------------------------------------------------------------------
// Kernel 3: s[b,l,h] = gamma_h * (sum_e (q_raw . Wq[e,:])^4)^(-1/4).
// ---------------------------------------------------------------------------
__global__ __launch_bounds__(256) void k3_scales(const float* __restrict__ queries,
                                                 const float* __restrict__ Wq,
                                                 const float* __restrict__ gamma) {
    __shared__ float sWqt[4096];
    __shared__ float sq[8 * 512];
    __shared__ float sg[8];

    int t = threadIdx.x;
    size_t R0 = (size_t)blockIdx.x * 8;

    for (int idx = t; idx < 4096; idx += 256) {
        int e = idx >> 6, d = idx & 63;
        sWqt[d * 64 + e] = Wq[idx];
    }
    for (int idx = t; idx < 4096; idx += 256) sq[idx] = queries[R0 * 512 + idx];
    if (t < 8) sg[t] = gamma[t];
    __syncthreads();

    int w = t >> 5, lane = t & 31;
    for (int task = w; task < 16; task += 8) {
        int hh = task & 7, rg = task >> 3;
        u64 acc[4] = {0ull, 0ull, 0ull, 0ull};
        for (int d = 0; d < 64; d++) {
            u64 w2 = *(const u64*)&sWqt[d * 64 + 2 * lane];
#pragma unroll
            for (int rr = 0; rr < 4; rr++) {
                float qv = sq[(rg * 4 + rr) * 512 + hh * 64 + d];
                acc[rr] = fma2(pack2(qv, qv), w2, acc[rr]);
            }
        }
#pragma unroll
        for (int rr = 0; rr < 4; rr++) {
            float a, bv;
            unpack2(acc[rr], a, bv);
            float p = (a * a) * (a * a) + (bv * bv) * (bv * bv);
#pragma unroll
            for (int o = 16; o > 0; o >>= 1) p += __shfl_xor_sync(0xffffffffu, p, o);
            if (lane == 0) g_S[(R0 + rg * 4 + rr) * CH + hh] = sg[hh] * rsqrtf(sqrtf(p));
        }
    }
}

// ---------------------------------------------------------------------------
// Kernel 4: warp-mma bf16 3-pass GEMM. CTA tile M=64, N=256, K=512 (32x k16).
// 8 warps, warp tile 32x64. Double-buffered smem, cp.async for B, on-the-fly
// fp32->bf16 hi/lo conversion (scale folded) for A. Grid (2, 128, 8) x 256.
// Stage layout (20480 B): Ahi[0,2048) Alo[2048,4096) Bhi[4096,12288) Blo[12288,20480)
// ---------------------------------------------------------------------------
__global__ __launch_bounds__(256) void k4_mma(const float* __restrict__ queries,
                                              const float* __restrict__ bo,
                                              float* __restrict__ out) {
    constexpr int ST = 20480;
    __shared__ __align__(16) char tiles[2][ST];

    int b = blockIdx.z, mt = blockIdx.y, nb = blockIdx.x;
    int t = threadIdx.x, wid = t >> 5, lane = t & 31;
    int wm = wid >> 2, wn = wid & 3;
    size_t rowbase = (size_t)b * CL + (size_t)mt * 64;
    int f0 = nb * 256;

    uint32_t stadr[2] = { smem_u32(&tiles[0][0]), smem_u32(&tiles[1][0]) };

    // A conversion role: thread -> (row, 4-float group)
    int arow = t >> 2, aq4 = t & 3;
    const float* asrc = queries + (rowbase + arow) * 512 + aq4 * 4;
    uint32_t aoff = (uint32_t)arow * 32
                  + (((uint32_t)(aq4 >> 1) ^ ((arow >> 2) & 1)) * 16)
                  + (aq4 & 1) * 8;
    float sreg[8];
#pragma unroll
    for (int h = 0; h < 8; h++) sreg[h] = g_S[(rowbase + arow) * 8 + h];

    // B copy role: thread t -> B row t (hi & lo, 2 chunks each).
    // FIX (R5 bug): store offsets must include the Bhi region base (+4096),
    // matching the ldmatrix read offsets. Blo region base = 12288 = bo0+8192.
    const char* bh_src = (const char*)(g_Gt_hi + ((size_t)b * 512 + f0 + t) * 512);
    const char* bl_src = (const char*)(g_Gt_lo + ((size_t)b * 512 + f0 + t) * 512);
    uint32_t bsw = (((uint32_t)t >> 2) & 1);
    uint32_t bo0 = 4096u + (uint32_t)t * 32 + ((0u ^ bsw) * 16);
    uint32_t bo1 = 4096u + (uint32_t)t * 32 + ((1u ^ bsw) * 16);

    // ldmatrix per-lane offsets
    int lrA = (lane & 7) + (lane & 8);
    int lcA = (lane >> 4) & 1;
    uint32_t am_off[2];
#pragma unroll
    for (int m2 = 0; m2 < 2; m2++) {
        int row = wm * 32 + m2 * 16 + lrA;
        am_off[m2] = (uint32_t)row * 32 + ((uint32_t)(lcA ^ ((row >> 2) & 1)) * 16);
    }
    int lrB = (lane & 7) + ((lane >> 4) & 1) * 8;
    int lcB = (lane >> 3) & 1;
    uint32_t bp_off[4];
#pragma unroll
    for (int p = 0; p < 4; p++) {
        int row = wn * 64 + p * 16 + lrB;
        bp_off[p] = 4096u + (uint32_t)row * 32 + ((uint32_t)(lcB ^ ((row >> 2) & 1)) * 16);
    }

    float acc[2][8][4];
#pragma unroll
    for (int m2 = 0; m2 < 2; m2++)
#pragma unroll
        for (int nt = 0; nt < 8; nt++)
#pragma unroll
            for (int r = 0; r < 4; r++) acc[m2][nt][r] = 0.f;

    // prologue: iter 0 -> stage 0
    {
        float4 v = *(const float4*)(asrc);
        float sc = sreg[0];
        float x0 = v.x * sc, x1 = v.y * sc, x2 = v.z * sc, x3 = v.w * sc;
        __nv_bfloat16 h0 = __float2bfloat16(x0), h1 = __float2bfloat16(x1);
        __nv_bfloat16 h2 = __float2bfloat16(x2), h3 = __float2bfloat16(x3);
        uint2 hp = make_uint2(pack_bf(h0, h1), pack_bf(h2, h3));
        uint2 lp = make_uint2(
            pack_bf(__float2bfloat16(x0 - __bfloat162float(h0)),
                    __float2bfloat16(x1 - __bfloat162float(h1))),
            pack_bf(__float2bfloat16(x2 - __bfloat162float(h2)),
                    __float2bfloat16(x3 - __bfloat162float(h3))));
        *(uint2*)(&tiles[0][aoff]) = hp;
        *(uint2*)(&tiles[0][2048 + aoff]) = lp;
        cp16(stadr[0] + bo0, bh_src + 0);
        cp16(stadr[0] + bo1, bh_src + 16);
        cp16(stadr[0] + 8192 + bo0, bl_src + 0);
        cp16(stadr[0] + 8192 + bo1, bl_src + 16);
        CP_COMMIT();
    }

    for (int it = 0; it < 32; it++) {
        int s = it & 1;
        uint32_t sb = stadr[s];
        uint32_t nbadr = stadr[s ^ 1];

        CP_WAIT(0);
        __syncthreads();

        float4 pv;
        if (it + 1 < 32) {
            pv = *(const float4*)(asrc + (it + 1) * 16);
            cp16(nbadr + bo0, bh_src + (it + 1) * 32);
            cp16(nbadr + bo1, bh_src + (it + 1) * 32 + 16);
            cp16(nbadr + 8192 + bo0, bl_src + (it + 1) * 32);
            cp16(nbadr + 8192 + bo1, bl_src + (it + 1) * 32 + 16);
            CP_COMMIT();
        }

        // fragments + mma
        uint32_t ah[2][4], al[2][4];
        ldsm4(ah[0], sb + am_off[0]);
        ldsm4(ah[1], sb + am_off[1]);
        ldsm4(al[0], sb + 2048 + am_off[0]);
        ldsm4(al[1], sb + 2048 + am_off[1]);
#pragma unroll
        for (int p = 0; p < 4; p++) {
            uint32_t bh4[4], bl4[4];
            ldsm4(bh4, sb + bp_off[p]);
            ldsm4(bl4, sb + 8192 + bp_off[p]);
#pragma unroll
            for (int j = 0; j < 2; j++)
#pragma unroll
                for (int m2 = 0; m2 < 2; m2++)
                    mma16816(acc[m2][p * 2 + j], ah[m2], &bh4[j * 2]);
#pragma unroll
            for (int j = 0; j < 2; j++)
#pragma unroll
                for (int m2 = 0; m2 < 2; m2++)
                    mma16816(acc[m2][p * 2 + j], ah[m2], &bl4[j * 2]);
#pragma unroll
            for (int j = 0; j < 2; j++)
#pragma unroll
                for (int m2 = 0; m2 < 2; m2++)
                    mma16816(acc[m2][p * 2 + j], al[m2], &bh4[j * 2]);
        }

        if (it + 1 < 32) {
            float sc = sreg[(it + 1) >> 2];
            float x0 = pv.x * sc, x1 = pv.y * sc, x2 = pv.z * sc, x3 = pv.w * sc;
            __nv_bfloat16 h0 = __float2bfloat16(x0), h1 = __float2bfloat16(x1);
            __nv_bfloat16 h2 = __float2bfloat16(x2), h3 = __float2bfloat16(x3);
            uint2 hp = make_uint2(pack_bf(h0, h1), pack_bf(h2, h3));
            uint2 lp = make_uint2(
                pack_bf(__float2bfloat16(x0 - __bfloat162float(h0)),
                        __float2bfloat16(x1 - __bfloat162float(h1))),
                pack_bf(__float2bfloat16(x2 - __bfloat162float(h2)),
                        __float2bfloat16(x3 - __bfloat162float(h3))));
            *(uint2*)(&tiles[s ^ 1][aoff]) = hp;
            *(uint2*)(&tiles[s ^ 1][2048 + aoff]) = lp;
        }
    }

    // epilogue: add bias, write fp32
    int r0 = lane >> 2, cbase = 2 * (lane & 3);
#pragma unroll
    for (int m2 = 0; m2 < 2; m2++) {
        size_t row = rowbase + wm * 32 + m2 * 16 + r0;
        float* orow0 = out + row * 512 + f0 + wn * 64;
        float* orow1 = orow0 + (size_t)8 * 512;
        const float* bp = bo + f0 + wn * 64;
#pragma unroll
        for (int nt = 0; nt < 8; nt++) {
            int col = nt * 8 + cbase;
            float b0v = bp[col], b1v = bp[col + 1];
            float2 v0 = make_float2(acc[m2][nt][0] + b0v, acc[m2][nt][1] + b1v);
            float2 v1 = make_float2(acc[m2][nt][2] + b0v, acc[m2][nt][3] + b1v);
            *(float2*)(orow0 + col) = v0;
            *(float2*)(orow1 + col) = v1;
        }
    }
}

// ---------------------------------------------------------------------------
extern "C" void kernel_launch(void* const* d_in, const int* in_sizes, int n_in,
                              void* d_out, int out_size) {
    const float* queries = (const float*)d_in[0];
    const float* keys    = (const float*)d_in[1];
    const float* values  = (const float*)d_in[2];
    const float* Wq      = (const float*)d_in[3];
    const float* Wk      = (const float*)d_in[4];
    const float* Wv      = (const float*)d_in[5];
    const float* Wo      = (const float*)d_in[6];
    const float* bo      = (const float*)d_in[7];
    const float* gamma   = (const float*)d_in[8];
    float* out = (float*)d_out;

    k1_moment<<<CB * CH * NCH, 256>>>(keys, values);
    k2_prepG<<<CB * CH, 256>>>(Wq, Wk, Wv, Wo, gamma);
    k3_scales<<<CB * CL / 8, 256>>>(queries, Wq, gamma);
    k4_mma<<<dim3(2, CL / 64, CB), 256>>>(queries, bo, out);
}

// round 13
// speedup vs baseline: 1.7887x; 1.2824x over previous
#include <cuda_runtime.h>
#include <cuda_bf16.h>
#include <cstdint>

// ---------------------------------------------------------------------------
// UFOAttention restructured:
//   M[b,h]  = sum_l outer(k_raw[b,l,h,:], v_raw[b,l,h,:])            (k1)
//   kv = Wk M Wv^T ; kv_n = xnorm ; P = Wq^T kv_n ; G = P Wo_h^T ;
//   Gt (transposed, split to bf16 hi/lo)                              (k2)
//   s[b,l,h] = gamma_h / ||q_raw[b,l,h,:] Wq^T||_4  (mma 3-pass)      (k3)
//   out[b]  = diag(s)*Q_raw @ Gbig + bo  via mma.sync bf16 3-pass     (k4)
// Plain sm_103-legal instructions only (no tcgen05 — target lacks 'a').
// ---------------------------------------------------------------------------

constexpr int CB = 8;
constexpr int CL = 8192;
constexpr int CH = 8;
constexpr int CD = 64;
constexpr int CE = 512;
constexpr int NCH = 16;
constexpr int CHUNK = CL / NCH;   // 512

__device__ float g_Mpart[CB * CH * NCH * CD * CD];
__device__ float g_S[CB * CL * CH];
__device__ __nv_bfloat16 g_Gt_hi[CB * CE * CE];   // [b][f][k]
__device__ __nv_bfloat16 g_Gt_lo[CB * CE * CE];

typedef unsigned long long u64;

__device__ __forceinline__ u64 pack2(float a, float b) {
    u64 r; asm("mov.b64 %0, {%1,%2};" : "=l"(r) : "f"(a), "f"(b)); return r;
}
__device__ __forceinline__ void unpack2(u64 v, float& a, float& b) {
    asm("mov.b64 {%0,%1}, %2;" : "=f"(a), "=f"(b) : "l"(v));
}
__device__ __forceinline__ u64 fma2(u64 a, u64 b, u64 c) {
    u64 d; asm("fma.rn.f32x2 %0, %1, %2, %3;" : "=l"(d) : "l"(a), "l"(b), "l"(c)); return d;
}
__device__ __forceinline__ uint32_t smem_u32(const void* p) {
    uint32_t a;
    asm("{ .reg .u64 t; cvta.to.shared.u64 t, %1; cvt.u32.u64 %0, t; }" : "=r"(a) : "l"(p));
    return a;
}
#define CP_COMMIT() asm volatile("cp.async.commit_group;" ::: "memory")
#define CP_WAIT(n)  asm volatile("cp.async.wait_group %0;" :: "n"(n) : "memory")
__device__ __forceinline__ void cp16(uint32_t dst, const void* src) {
    asm volatile("cp.async.ca.shared.global [%0], [%1], 16;" :: "r"(dst), "l"(src) : "memory");
}
__device__ __forceinline__ void ldsm4(uint32_t* r, uint32_t a) {
    asm volatile("ldmatrix.sync.aligned.m8n8.x4.shared.b16 {%0,%1,%2,%3}, [%4];"
                 : "=r"(r[0]), "=r"(r[1]), "=r"(r[2]), "=r"(r[3]) : "r"(a));
}
__device__ __forceinline__ void mma16816(float* c, const uint32_t* a, const uint32_t* b) {
    asm volatile("mma.sync.aligned.m16n8k16.row.col.f32.bf16.bf16.f32 "
                 "{%0,%1,%2,%3}, {%4,%5,%6,%7}, {%8,%9}, {%0,%1,%2,%3};"
                 : "+f"(c[0]), "+f"(c[1]), "+f"(c[2]), "+f"(c[3])
                 : "r"(a[0]), "r"(a[1]), "r"(a[2]), "r"(a[3]), "r"(b[0]), "r"(b[1]));
}
__device__ __forceinline__ uint32_t pack_bf(__nv_bfloat16 a, __nv_bfloat16 b) {
    unsigned short x = *(unsigned short*)&a, y = *(unsigned short*)&b;
    return (uint32_t)x | ((uint32_t)y << 16);
}
// convert 8 scaled floats -> 8 bf16 hi (uint4) + 8 bf16 lo (uint4)
__device__ __forceinline__ void conv8(float4 v0, float4 v1, float sc,
                                      uint4& hi, uint4& lo) {
    float x[8] = {v0.x * sc, v0.y * sc, v0.z * sc, v0.w * sc,
                  v1.x * sc, v1.y * sc, v1.z * sc, v1.w * sc};
    __nv_bfloat16 h[8], l[8];
#pragma unroll
    for (int i = 0; i < 8; i++) {
        h[i] = __float2bfloat16(x[i]);
        l[i] = __float2bfloat16(x[i] - __bfloat162float(h[i]));
    }
    hi = make_uint4(pack_bf(h[0], h[1]), pack_bf(h[2], h[3]),
                    pack_bf(h[4], h[5]), pack_bf(h[6], h[7]));
    lo = make_uint4(pack_bf(l[0], l[1]), pack_bf(l[2], l[3]),
                    pack_bf(l[4], l[5]), pack_bf(l[6], l[7]));
}

// ---------------------------------------------------------------------------
// Kernel 1: partial raw moments, 3-stage cp.async pipeline, 16 rows/stage.
// ---------------------------------------------------------------------------
__global__ __launch_bounds__(256) void k1_moment(const float* __restrict__ keys,
                                                 const float* __restrict__ values) {
    constexpr int RS = 16;
    constexpr int NIT = CHUNK / RS;   // 32
    __shared__ __align__(16) float sk[3][RS][64];
    __shared__ __align__(16) float sv[3][RS][64];

    int blk = blockIdx.x;
    int chunk = blk % NCH;
    int bh = blk / NCH;
    int hh = bh % CH, b = bh / CH;
    int t = threadIdx.x;
    int ti = t >> 4, tj = t & 15;
    int crow = t >> 4, cc = t & 15;

    const float* kb = keys   + (size_t)b * CL * CE + hh * CD;
    const float* vb = values + (size_t)b * CL * CE + hh * CD;
    int l0 = chunk * CHUNK;

    u64 acc[4][2];
#pragma unroll
    for (int r = 0; r < 4; r++) { acc[r][0] = 0ull; acc[r][1] = 0ull; }

#pragma unroll
    for (int pit = 0; pit < 2; pit++) {
        size_t l = (size_t)(l0 + pit * RS + crow);
        cp16(smem_u32(&sk[pit][crow][cc * 4]), kb + l * CE + cc * 4);
        cp16(smem_u32(&sv[pit][crow][cc * 4]), vb + l * CE + cc * 4);
        CP_COMMIT();
    }

    for (int it = 0; it < NIT; it++) {
        int s = it % 3;
        if (it < NIT - 1) CP_WAIT(1); else CP_WAIT(0);
        __syncthreads();
        if (it + 2 < NIT) {
            int ns = (it + 2) % 3;
            size_t l = (size_t)(l0 + (it + 2) * RS + crow);
            cp16(smem_u32(&sk[ns][crow][cc * 4]), kb + l * CE + cc * 4);
            cp16(smem_u32(&sv[ns][crow][cc * 4]), vb + l * CE + cc * 4);
            CP_COMMIT();
        }
#pragma unroll
        for (int r = 0; r < RS; r++) {
            u64 kk[4];
#pragma unroll
            for (int rr = 0; rr < 4; rr++) {
                float kv_ = sk[s][r][4 * ti + rr];
                kk[rr] = pack2(kv_, kv_);
            }
            u64 v0 = *(const u64*)&sv[s][r][4 * tj];
            u64 v1 = *(const u64*)&sv[s][r][4 * tj + 2];
#pragma unroll
            for (int rr = 0; rr < 4; rr++) {
                acc[rr][0] = fma2(kk[rr], v0, acc[rr][0]);
                acc[rr][1] = fma2(kk[rr], v1, acc[rr][1]);
            }
        }
    }

    float* Mp = g_Mpart + ((size_t)bh * NCH + chunk) * (CD * CD);
#pragma unroll
    for (int r = 0; r < 4; r++) {
        float a, bv, c, dv;
        unpack2(acc[r][0], a, bv);
        unpack2(acc[r][1], c, dv);
        int row = 4 * ti + r;
        Mp[row * 64 + 4 * tj + 0] = a;
        Mp[row * 64 + 4 * tj + 1] = bv;
        Mp[row * 64 + 4 * tj + 2] = c;
        Mp[row * 64 + 4 * tj + 3] = dv;
    }
}

// ---------------------------------------------------------------------------
// Kernel 2: per (b,h) G = Wq^T xnorm(Wk M Wv^T) Wo_h^T -> Gt hi/lo bf16.
// ---------------------------------------------------------------------------
__global__ __launch_bounds__(256) void k2_prepG(const float* __restrict__ Wq,
                                                const float* __restrict__ Wk,
                                                const float* __restrict__ Wv,
                                                const float* __restrict__ Wo,
                                                const float* __restrict__ gamma) {
    __shared__ float sA[4096];
    __shared__ float sB[4096];
    __shared__ float rs[64];

    int bh = blockIdx.x;
    int hh = bh & 7, b = bh >> 3;
    int t = threadIdx.x;
    int i0 = (t >> 4) * 4, j0 = (t & 15) * 4;

    for (int idx = t; idx < 4096; idx += 256) {
        float s = 0.f;
#pragma unroll
        for (int c = 0; c < NCH; c++) s += g_Mpart[((size_t)bh * NCH + c) * 4096 + idx];
        sA[idx] = s;
        sB[idx] = Wv[idx];
    }
    __syncthreads();

    float r16[4][4];

    // Stage 1: T[i,e] = sum_j M[i,j] Wv[e,j]
#pragma unroll
    for (int r = 0; r < 4; r++)
#pragma unroll
        for (int c = 0; c < 4; c++) r16[r][c] = 0.f;
    for (int j = 0; j < 64; j++) {
        float a[4], bv[4];
#pragma unroll
        for (int r = 0; r < 4; r++) a[r] = sA[(i0 + r) * 64 + j];
#pragma unroll
        for (int c = 0; c < 4; c++) bv[c] = sB[(j0 + c) * 64 + j];
#pragma unroll
        for (int r = 0; r < 4; r++)
#pragma unroll
            for (int c = 0; c < 4; c++) r16[r][c] += a[r] * bv[c];
    }
    __syncthreads();
#pragma unroll
    for (int r = 0; r < 4; r++)
#pragma unroll
        for (int c = 0; c < 4; c++) sA[(i0 + r) * 64 + j0 + c] = r16[r][c];
    for (int idx = t; idx < 4096; idx += 256) sB[idx] = Wk[idx];
    __syncthreads();

    // Stage 2: kv[d,e] = sum_i Wk[d,i] T[i,e]
#pragma unroll
    for (int r = 0; r < 4; r++)
#pragma unroll
        for (int c = 0; c < 4; c++) r16[r][c] = 0.f;
    for (int i = 0; i < 64; i++) {
        float a[4], bv[4];
#pragma unroll
        for (int r = 0; r < 4; r++) a[r] = sB[(i0 + r) * 64 + i];
#pragma unroll
        for (int c = 0; c < 4; c++) bv[c] = sA[i * 64 + j0 + c];
#pragma unroll
        for (int r = 0; r < 4; r++)
#pragma unroll
            for (int c = 0; c < 4; c++) r16[r][c] += a[r] * bv[c];
    }
    __syncthreads();
#pragma unroll
    for (int r = 0; r < 4; r++)
#pragma unroll
        for (int c = 0; c < 4; c++) sA[(i0 + r) * 64 + j0 + c] = r16[r][c];
    for (int idx = t; idx < 4096; idx += 256) sB[idx] = Wq[idx];
    __syncthreads();

    // Stage 3: rs[d] = gamma_h * (sum_e kv[d,e]^4)^(-1/4)
    {
        int w = t >> 5, lane = t & 31;
        float g = gamma[hh];
        for (int d = w * 8; d < w * 8 + 8; d++) {
            float x1 = sA[d * 64 + lane], x2 = sA[d * 64 + lane + 32];
            float p = (x1 * x1) * (x1 * x1) + (x2 * x2) * (x2 * x2);
#pragma unroll
            for (int o = 16; o > 0; o >>= 1) p += __shfl_xor_sync(0xffffffffu, p, o);
            if (lane == 0) rs[d] = g * rsqrtf(sqrtf(p));
        }
    }
    __syncthreads();
    for (int idx = t; idx < 4096; idx += 256) sA[idx] *= rs[idx >> 6];
    __syncthreads();

    // Stage 4: P[i,e] = sum_d Wq[d,i] kv_n[d,e]
#pragma unroll
    for (int r = 0; r < 4; r++)
#pragma unroll
        for (int c = 0; c < 4; c++) r16[r][c] = 0.f;
    for (int d = 0; d < 64; d++) {
        float a[4], bv[4];
#pragma unroll
        for (int r = 0; r < 4; r++) a[r] = sB[d * 64 + i0 + r];
#pragma unroll
        for (int c = 0; c < 4; c++) bv[c] = sA[d * 64 + j0 + c];
#pragma unroll
        for (int r = 0; r < 4; r++)
#pragma unroll
            for (int c = 0; c < 4; c++) r16[r][c] += a[r] * bv[c];
    }
    __syncthreads();
#pragma unroll
    for (int r = 0; r < 4; r++)
#pragma unroll
        for (int c = 0; c < 4; c++) sA[(i0 + r) * 64 + j0 + c] = r16[r][c];
    __syncthreads();

    // Stage 5: G[i,f] = sum_e P[i,e] Wo[f, h*64+e] -> Gt hi/lo
    for (int fb = 0; fb < 8; fb++) {
        for (int idx = t; idx < 4096; idx += 256) {
            int ff = idx >> 6, e = idx & 63;
            sB[idx] = Wo[(size_t)(fb * 64 + ff) * 512 + hh * 64 + e];
        }
        __syncthreads();
#pragma unroll
        for (int r = 0; r < 4; r++)
#pragma unroll
            for (int c = 0; c < 4; c++) r16[r][c] = 0.f;
        for (int e = 0; e < 64; e++) {
            float a[4], bv[4];
#pragma unroll
            for (int r = 0; r < 4; r++) a[r] = sA[(i0 + r) * 64 + e];
#pragma unroll
            for (int c = 0; c < 4; c++) bv[c] = sB[(j0 + c) * 64 + e];
#pragma unroll
            for (int r = 0; r < 4; r++)
#pragma unroll
                for (int c = 0; c < 4; c++) r16[r][c] += a[r] * bv[c];
        }
#pragma unroll
        for (int r = 0; r < 4; r++)
#pragma unroll
            for (int c = 0; c < 4; c++) {
                float val = r16[r][c];
                __nv_bfloat16 vh = __float2bfloat16(val);
                __nv_bfloat16 vl = __float2bfloat16(val - __bfloat162float(vh));
                size_t p = ((size_t)b * 512 + fb * 64 + j0 + c) * 512 + hh * 64 + i0 + r;
                g_Gt_hi[p] = vh;
                g_Gt_lo[p] = vl;
            }
        __syncthreads();
    }
}

// ---------------------------------------------------------------------------
// Kernel 3 (tensor): per block, 64 rows x all heads. Qp = q @ Wq^T per head
// via 3-pass split-bf16 mma; fused L4-norm reduction on fragments -> g_S.
// Grid: CB*CL/64 = 1024 blocks x 256 threads (8 warps; 2 heads in flight).
// smem 48KB: Whi[0,8K) Wlo[8K,16K) Q[hsel]: hi at 16K+hsel*16K, lo +8K.
// Rows are 128B (64 bf16), xor-(row&7) swizzle on 16B chunks.
// ---------------------------------------------------------------------------
__global__ __launch_bounds__(256) void k3_mma(const float* __restrict__ queries,
                                              const float* __restrict__ Wq,
                                              const float* __restrict__ gamma) {
    __shared__ __align__(16) char sm[49152];
    uint32_t sb = smem_u32(sm);
    int t = threadIdx.x, wid = t >> 5, lane = t & 31;
    size_t R0 = (size_t)blockIdx.x * 64;

    // --- convert Wq (fp32 [e][d]) -> bf16 hi/lo, swizzled ---
    {
        int row = t >> 2, c2 = t & 3;          // row=e, two 16B chunks
        const float* src = Wq + row * 64 + c2 * 16;
        float4 v0 = *(const float4*)(src);
        float4 v1 = *(const float4*)(src + 4);
        float4 v2 = *(const float4*)(src + 8);
        float4 v3 = *(const float4*)(src + 12);
        uint4 h0, l0, h1, l1;
        conv8(v0, v1, 1.f, h0, l0);
        conv8(v2, v3, 1.f, h1, l1);
        uint32_t o0 = (uint32_t)row * 128 + (((2 * c2) ^ (row & 7)) * 16);
        uint32_t o1 = (uint32_t)row * 128 + (((2 * c2 + 1) ^ (row & 7)) * 16);
        *(uint4*)(sm + o0) = h0;
        *(uint4*)(sm + o1) = h1;
        *(uint4*)(sm + 8192 + o0) = l0;
        *(uint4*)(sm + 8192 + o1) = l1;
    }

    // warp roles
    int hsel = wid >> 2, mtile = wid & 3;
    int lrA = (lane & 7) + (lane & 8);
    int lcA = (lane >> 4) & 1;
    int lrB = (lane & 7) + ((lane >> 4) & 1) * 8;
    int lcB = (lane >> 3) & 1;
    int arow = mtile * 16 + lrA;
    uint32_t qbase = 16384u + (uint32_t)hsel * 16384u;
    uint32_t aoff_row = qbase + (uint32_t)arow * 128;
    int asw = arow & 7;

    for (int hp = 0; hp < 4; hp++) {
        __syncthreads();   // previous hp's MMAs done before overwriting q bufs
        // --- convert q slices for heads 2hp, 2hp+1 ---
        {
            int row = t >> 2, c2 = t & 3;
#pragma unroll
            for (int hs = 0; hs < 2; hs++) {
                int h = 2 * hp + hs;
                const float* src = queries + (R0 + row) * 512 + h * 64 + c2 * 16;
                float4 v0 = *(const float4*)(src);
                float4 v1 = *(const float4*)(src + 4);
                float4 v2 = *(const float4*)(src + 8);
                float4 v3 = *(const float4*)(src + 12);
                uint4 h0, l0, h1, l1;
                conv8(v0, v1, 1.f, h0, l0);
                conv8(v2, v3, 1.f, h1, l1);
                uint32_t qb = 16384u + (uint32_t)hs * 16384u;
                uint32_t o0 = qb + (uint32_t)row * 128 + (((2 * c2) ^ (row & 7)) * 16);
                uint32_t o1 = qb + (uint32_t)row * 128 + (((2 * c2 + 1) ^ (row & 7)) * 16);
                *(uint4*)(sm + o0) = h0;
                *(uint4*)(sm + o1) = h1;
                *(uint4*)(sm + 8192 + o0) = l0;
                *(uint4*)(sm + 8192 + o1) = l1;
            }
        }
        __syncthreads();

        int h = 2 * hp + hsel;
        float acc[8][4];
#pragma unroll
        for (int j = 0; j < 8; j++)
#pragma unroll
            for (int r = 0; r < 4; r++) acc[j][r] = 0.f;

#pragma unroll
        for (int k16 = 0; k16 < 4; k16++) {
            uint32_t ah[4], al[4];
            uint32_t ao = aoff_row + (((k16 * 2 + lcA) ^ asw) * 16);
            ldsm4(ah, sb + ao);
            ldsm4(al, sb + 8192 + ao);
#pragma unroll
            for (int p = 0; p < 4; p++) {
                int brow = p * 16 + lrB;
                uint32_t bo = (uint32_t)brow * 128 + (((k16 * 2 + lcB) ^ (brow & 7)) * 16);
                uint32_t bh4[4], bl4[4];
                ldsm4(bh4, sb + bo);
                ldsm4(bl4, sb + 8192 + bo);
#pragma unroll
                for (int j = 0; j < 2; j++) {
                    mma16816(acc[p * 2 + j], ah, &bh4[j * 2]);
                    mma16816(acc[p * 2 + j], ah, &bl4[j * 2]);
                    mma16816(acc[p * 2 + j], al, &bh4[j * 2]);
                }
            }
        }

        // --- fused L4 norm: rows r0=lane>>2 (acc[.][0,1]) and r0+8 ([2,3]) ---
        float p0 = 0.f, p1 = 0.f;
#pragma unroll
        for (int j = 0; j < 8; j++) {
            float a0 = acc[j][0], a1 = acc[j][1];
            float a2 = acc[j][2], a3 = acc[j][3];
            p0 += (a0 * a0) * (a0 * a0) + (a1 * a1) * (a1 * a1);
            p1 += (a2 * a2) * (a2 * a2) + (a3 * a3) * (a3 * a3);
        }
#pragma unroll
        for (int o = 1; o <= 2; o <<= 1) {
            p0 += __shfl_xor_sync(0xffffffffu, p0, o);
            p1 += __shfl_xor_sync(0xffffffffu, p1, o);
        }
        if ((lane & 3) == 0) {
            float gm = __ldg(&gamma[h]);
            size_t row0 = R0 + mtile * 16 + (lane >> 2);
            g_S[row0 * CH + h] = gm * rsqrtf(sqrtf(p0));
            g_S[(row0 + 8) * CH + h] = gm * rsqrtf(sqrtf(p1));
        }
    }
}

// ---------------------------------------------------------------------------
// Kernel 4: warp-mma bf16 3-pass GEMM. CTA tile M=128, N=256, K=512.
// 8 warps (2x4), warp tile 64x64. Double-buffered smem, cp.async for B,
// on-the-fly fp32->bf16 hi/lo conversion (scale folded) for A.
// Grid (2, 64, 8) x 256. Stage (24576 B): Ahi[0,4K) Alo[4K,8K) Bhi[8K,16K) Blo[16K,24K)
// ---------------------------------------------------------------------------
__global__ __launch_bounds__(256) void k4_mma(const float* __restrict__ queries,
                                              const float* __restrict__ bo,
                                              float* __restrict__ out) {
    constexpr int ST = 24576;
    __shared__ __align__(16) char tiles[2][ST];

    int b = blockIdx.z, mt = blockIdx.y, nb = blockIdx.x;
    int t = threadIdx.x, wid = t >> 5, lane = t & 31;
    int wm = wid >> 2, wn = wid & 3;          // wm: 2 m64 tiles, wn: 4 n64 tiles
    size_t rowbase = (size_t)b * CL + (size_t)mt * 128;
    int f0 = nb * 256;

    uint32_t stadr[2] = { smem_u32(&tiles[0][0]), smem_u32(&tiles[1][0]) };

    // A conversion role: thread -> (row, 8-float half)
    int arow = t >> 1, aq8 = t & 1;
    const float* asrc = queries + (rowbase + arow) * 512 + aq8 * 8;
    uint32_t aoff = (uint32_t)arow * 32 + (((uint32_t)aq8 ^ ((arow >> 2) & 1)) * 16);
    const float* srow = g_S + (rowbase + arow) * 8;

    // B copy role: thread t -> B row t (hi & lo, 2 x 16B chunks each)
    const char* bh_src = (const char*)(g_Gt_hi + ((size_t)b * 512 + f0 + t) * 512);
    const char* bl_src = (const char*)(g_Gt_lo + ((size_t)b * 512 + f0 + t) * 512);
    uint32_t bsw = (((uint32_t)t >> 2) & 1);
    uint32_t bo0 = 8192u + (uint32_t)t * 32 + ((0u ^ bsw) * 16);
    uint32_t bo1 = 8192u + (uint32_t)t * 32 + ((1u ^ bsw) * 16);

    // ldmatrix per-lane offsets
    int lrA = (lane & 7) + (lane & 8);
    int lcA = (lane >> 4) & 1;
    uint32_t am_off[4];
#pragma unroll
    for (int m2 = 0; m2 < 4; m2++) {
        int row = wm * 64 + m2 * 16 + lrA;
        am_off[m2] = (uint32_t)row * 32 + ((uint32_t)(lcA ^ ((row >> 2) & 1)) * 16);
    }
    int lrB = (lane & 7) + ((lane >> 4) & 1) * 8;
    int lcB = (lane >> 3) & 1;
    uint32_t bp_off[4];
#pragma unroll
    for (int p = 0; p < 4; p++) {
        int row = wn * 64 + p * 16 + lrB;
        bp_off[p] = 8192u + (uint32_t)row * 32 + ((uint32_t)(lcB ^ ((row >> 2) & 1)) * 16);
    }

    float acc[4][8][4];
#pragma unroll
    for (int m2 = 0; m2 < 4; m2++)
#pragma unroll
        for (int nt = 0; nt < 8; nt++)
#pragma unroll
            for (int r = 0; r < 4; r++) acc[m2][nt][r] = 0.f;

    // prologue: iter 0 -> stage 0
    {
        float sc = __ldg(srow);
        float4 v0 = *(const float4*)(asrc);
        float4 v1 = *(const float4*)(asrc + 4);
        uint4 hp, lp;
        conv8(v0, v1, sc, hp, lp);
        *(uint4*)(&tiles[0][aoff]) = hp;
        *(uint4*)(&tiles[0][4096 + aoff]) = lp;
        cp16(stadr[0] + bo0, bh_src + 0);
        cp16(stadr[0] + bo1, bh_src + 16);
        cp16(stadr[0] + 8192 + bo0, bl_src + 0);
        cp16(stadr[0] + 8192 + bo1, bl_src + 16);
        CP_COMMIT();
    }

    for (int it = 0; it < 32; it++) {
        int s = it & 1;
        uint32_t sbadr = stadr[s];
        uint32_t nbadr = stadr[s ^ 1];

        CP_WAIT(0);
        __syncthreads();

        float4 pv0, pv1;
        float psc;
        if (it + 1 < 32) {
            psc = __ldg(srow + ((it + 1) >> 2));
            pv0 = *(const float4*)(asrc + (it + 1) * 16);
            pv1 = *(const float4*)(asrc + (it + 1) * 16 + 4);
            cp16(nbadr + bo0, bh_src + (it + 1) * 32);
            cp16(nbadr + bo1, bh_src + (it + 1) * 32 + 16);
            cp16(nbadr + 8192 + bo0, bl_src + (it + 1) * 32);
            cp16(nbadr + 8192 + bo1, bl_src + (it + 1) * 32 + 16);
            CP_COMMIT();
        }

        // fragments + mma
        uint32_t ah[4][4], al[4][4];
#pragma unroll
        for (int m2 = 0; m2 < 4; m2++) {
            ldsm4(ah[m2], sbadr + am_off[m2]);
            ldsm4(al[m2], sbadr + 4096 + am_off[m2]);
        }
#pragma unroll
        for (int p = 0; p < 4; p++) {
            uint32_t bh4[4], bl4[4];
            ldsm4(bh4, sbadr + bp_off[p]);
            ldsm4(bl4, sbadr + 8192 + bp_off[p]);
#pragma unroll
            for (int j = 0; j < 2; j++)
#pragma unroll
                for (int m2 = 0; m2 < 4; m2++)
                    mma16816(acc[m2][p * 2 + j], ah[m2], &bh4[j * 2]);
#pragma unroll
            for (int j = 0; j < 2; j++)
#pragma unroll
                for (int m2 = 0; m2 < 4; m2++)
                    mma16816(acc[m2][p * 2 + j], ah[m2], &bl4[j * 2]);
#pragma unroll
            for (int j = 0; j < 2; j++)
#pragma unroll
                for (int m2 = 0; m2 < 4; m2++)
                    mma16816(acc[m2][p * 2 + j], al[m2], &bh4[j * 2]);
        }

        if (it + 1 < 32) {
            uint4 hp, lp;
            conv8(pv0, pv1, psc, hp, lp);
            *(uint4*)(&tiles[s ^ 1][aoff]) = hp;
            *(uint4*)(&tiles[s ^ 1][4096 + aoff]) = lp;
        }
    }

    // epilogue: add bias, write fp32
    int r0 = lane >> 2, cbase = 2 * (lane & 3);
#pragma unroll
    for (int m2 = 0; m2 < 4; m2++) {
        size_t row = rowbase + wm * 64 + m2 * 16 + r0;
        float* orow0 = out + row * 512 + f0 + wn * 64;
        float* orow1 = orow0 + (size_t)8 * 512;
        const float* bp = bo + f0 + wn * 64;
#pragma unroll
        for (int nt = 0; nt < 8; nt++) {
            int col = nt * 8 + cbase;
            float b0v = bp[col], b1v = bp[col + 1];
            float2 v0 = make_float2(acc[m2][nt][0] + b0v, acc[m2][nt][1] + b1v);
            float2 v1 = make_float2(acc[m2][nt][2] + b0v, acc[m2][nt][3] + b1v);
            *(float2*)(orow0 + col) = v0;
            *(float2*)(orow1 + col) = v1;
        }
    }
}

// ---------------------------------------------------------------------------
extern "C" void kernel_launch(void* const* d_in, const int* in_sizes, int n_in,
                              void* d_out, int out_size) {
    const float* queries = (const float*)d_in[0];
    const float* keys    = (const float*)d_in[1];
    const float* values  = (const float*)d_in[2];
    const float* Wq      = (const float*)d_in[3];
    const float* Wk      = (const float*)d_in[4];
    const float* Wv      = (const float*)d_in[5];
    const float* Wo      = (const float*)d_in[6];
    const float* bo      = (const float*)d_in[7];
    const float* gamma   = (const float*)d_in[8];
    float* out = (float*)d_out;

    k1_moment<<<CB * CH * NCH, 256>>>(keys, values);
    k2_prepG<<<CB * CH, 256>>>(Wq, Wk, Wv, Wo, gamma);
    k3_mma<<<CB * CL / 64, 256>>>(queries, Wq, gamma);
    k4_mma<<<dim3(2, CL / 128, CB), 256>>>(queries, bo, out);
}

// round 14
// speedup vs baseline: 1.9565x; 1.0938x over previous
#include <cuda_runtime.h>
#include <cuda_bf16.h>
#include <cstdint>

// ---------------------------------------------------------------------------
// UFOAttention restructured:
//   M[b,h]  = sum_l outer(k_raw[b,l,h,:], v_raw[b,l,h,:])            (k1)
//   kv = Wk M Wv^T ; kv_n = xnorm ; P = Wq^T kv_n ; G = P Wo_h^T ;
//   Gt (transposed, split to bf16 hi/lo)                              (k2)
//   s[b,l,h] = gamma_h / ||q_raw[b,l,h,:] Wq^T||_4  (mma 3-pass)      (k3)
//   out[b]  = diag(s)*Q_raw @ Gbig + bo  via mma.sync bf16 3-pass     (k4)
// Plain sm_103-legal instructions only (no tcgen05 — target lacks 'a').
// ---------------------------------------------------------------------------

constexpr int CB = 8;
constexpr int CL = 8192;
constexpr int CH = 8;
constexpr int CD = 64;
constexpr int CE = 512;
constexpr int NCH = 16;
constexpr int CHUNK = CL / NCH;   // 512

__device__ float g_Mpart[CB * CH * NCH * CD * CD];
__device__ float g_S[CB * CL * CH];
__device__ __nv_bfloat16 g_Gt_hi[CB * CE * CE];   // [b][f][k]
__device__ __nv_bfloat16 g_Gt_lo[CB * CE * CE];

typedef unsigned long long u64;

__device__ __forceinline__ u64 pack2(float a, float b) {
    u64 r; asm("mov.b64 %0, {%1,%2};" : "=l"(r) : "f"(a), "f"(b)); return r;
}
__device__ __forceinline__ void unpack2(u64 v, float& a, float& b) {
    asm("mov.b64 {%0,%1}, %2;" : "=f"(a), "=f"(b) : "l"(v));
}
__device__ __forceinline__ u64 fma2(u64 a, u64 b, u64 c) {
    u64 d; asm("fma.rn.f32x2 %0, %1, %2, %3;" : "=l"(d) : "l"(a), "l"(b), "l"(c)); return d;
}
__device__ __forceinline__ uint32_t smem_u32(const void* p) {
    uint32_t a;
    asm("{ .reg .u64 t; cvta.to.shared.u64 t, %1; cvt.u32.u64 %0, t; }" : "=r"(a) : "l"(p));
    return a;
}
#define CP_COMMIT() asm volatile("cp.async.commit_group;" ::: "memory")
#define CP_WAIT(n)  asm volatile("cp.async.wait_group %0;" :: "n"(n) : "memory")
__device__ __forceinline__ void cp16(uint32_t dst, const void* src) {
    asm volatile("cp.async.ca.shared.global [%0], [%1], 16;" :: "r"(dst), "l"(src) : "memory");
}
__device__ __forceinline__ void ldsm4(uint32_t* r, uint32_t a) {
    asm volatile("ldmatrix.sync.aligned.m8n8.x4.shared.b16 {%0,%1,%2,%3}, [%4];"
                 : "=r"(r[0]), "=r"(r[1]), "=r"(r[2]), "=r"(r[3]) : "r"(a));
}
__device__ __forceinline__ void mma16816(float* c, const uint32_t* a, const uint32_t* b) {
    asm volatile("mma.sync.aligned.m16n8k16.row.col.f32.bf16.bf16.f32 "
                 "{%0,%1,%2,%3}, {%4,%5,%6,%7}, {%8,%9}, {%0,%1,%2,%3};"
                 : "+f"(c[0]), "+f"(c[1]), "+f"(c[2]), "+f"(c[3])
                 : "r"(a[0]), "r"(a[1]), "r"(a[2]), "r"(a[3]), "r"(b[0]), "r"(b[1]));
}
__device__ __forceinline__ uint32_t pack_bf(__nv_bfloat16 a, __nv_bfloat16 b) {
    unsigned short x = *(unsigned short*)&a, y = *(unsigned short*)&b;
    return (uint32_t)x | ((uint32_t)y << 16);
}
// convert 8 scaled floats -> 8 bf16 hi (uint4) + 8 bf16 lo (uint4)
__device__ __forceinline__ void conv8(float4 v0, float4 v1, float sc,
                                      uint4& hi, uint4& lo) {
    float x[8] = {v0.x * sc, v0.y * sc, v0.z * sc, v0.w * sc,
                  v1.x * sc, v1.y * sc, v1.z * sc, v1.w * sc};
    __nv_bfloat16 h[8], l[8];
#pragma unroll
    for (int i = 0; i < 8; i++) {
        h[i] = __float2bfloat16(x[i]);
        l[i] = __float2bfloat16(x[i] - __bfloat162float(h[i]));
    }
    hi = make_uint4(pack_bf(h[0], h[1]), pack_bf(h[2], h[3]),
                    pack_bf(h[4], h[5]), pack_bf(h[6], h[7]));
    lo = make_uint4(pack_bf(l[0], l[1]), pack_bf(l[2], l[3]),
                    pack_bf(l[4], l[5]), pack_bf(l[6], l[7]));
}

// ---------------------------------------------------------------------------
// Kernel 1: partial raw moments, 3-stage cp.async pipeline, 16 rows/stage.
// ---------------------------------------------------------------------------
__global__ __launch_bounds__(256) void k1_moment(const float* __restrict__ keys,
                                                 const float* __restrict__ values) {
    constexpr int RS = 16;
    constexpr int NIT = CHUNK / RS;   // 32
    __shared__ __align__(16) float sk[3][RS][64];
    __shared__ __align__(16) float sv[3][RS][64];

    int blk = blockIdx.x;
    int chunk = blk % NCH;
    int bh = blk / NCH;
    int hh = bh % CH, b = bh / CH;
    int t = threadIdx.x;
    int ti = t >> 4, tj = t & 15;
    int crow = t >> 4, cc = t & 15;

    const float* kb = keys   + (size_t)b * CL * CE + hh * CD;
    const float* vb = values + (size_t)b * CL * CE + hh * CD;
    int l0 = chunk * CHUNK;

    u64 acc[4][2];
#pragma unroll
    for (int r = 0; r < 4; r++) { acc[r][0] = 0ull; acc[r][1] = 0ull; }

#pragma unroll
    for (int pit = 0; pit < 2; pit++) {
        size_t l = (size_t)(l0 + pit * RS + crow);
        cp16(smem_u32(&sk[pit][crow][cc * 4]), kb + l * CE + cc * 4);
        cp16(smem_u32(&sv[pit][crow][cc * 4]), vb + l * CE + cc * 4);
        CP_COMMIT();
    }

    for (int it = 0; it < NIT; it++) {
        int s = it % 3;
        if (it < NIT - 1) CP_WAIT(1); else CP_WAIT(0);
        __syncthreads();
        if (it + 2 < NIT) {
            int ns = (it + 2) % 3;
            size_t l = (size_t)(l0 + (it + 2) * RS + crow);
            cp16(smem_u32(&sk[ns][crow][cc * 4]), kb + l * CE + cc * 4);
            cp16(smem_u32(&sv[ns][crow][cc * 4]), vb + l * CE + cc * 4);
            CP_COMMIT();
        }
#pragma unroll
        for (int r = 0; r < RS; r++) {
            u64 kk[4];
#pragma unroll
            for (int rr = 0; rr < 4; rr++) {
                float kv_ = sk[s][r][4 * ti + rr];
                kk[rr] = pack2(kv_, kv_);
            }
            u64 v0 = *(const u64*)&sv[s][r][4 * tj];
            u64 v1 = *(const u64*)&sv[s][r][4 * tj + 2];
#pragma unroll
            for (int rr = 0; rr < 4; rr++) {
                acc[rr][0] = fma2(kk[rr], v0, acc[rr][0]);
                acc[rr][1] = fma2(kk[rr], v1, acc[rr][1]);
            }
        }
    }

    float* Mp = g_Mpart + ((size_t)bh * NCH + chunk) * (CD * CD);
#pragma unroll
    for (int r = 0; r < 4; r++) {
        float a, bv, c, dv;
        unpack2(acc[r][0], a, bv);
        unpack2(acc[r][1], c, dv);
        int row = 4 * ti + r;
        Mp[row * 64 + 4 * tj + 0] = a;
        Mp[row * 64 + 4 * tj + 1] = bv;
        Mp[row * 64 + 4 * tj + 2] = c;
        Mp[row * 64 + 4 * tj + 3] = dv;
    }
}

// ---------------------------------------------------------------------------
// Kernel 2: per (b,h) G = Wq^T xnorm(Wk M Wv^T) Wo_h^T -> Gt hi/lo bf16.
// ---------------------------------------------------------------------------
__global__ __launch_bounds__(256) void k2_prepG(const float* __restrict__ Wq,
                                                const float* __restrict__ Wk,
                                                const float* __restrict__ Wv,
                                                const float* __restrict__ Wo,
                                                const float* __restrict__ gamma) {
    __shared__ float sA[4096];
    __shared__ float sB[4096];
    __shared__ float rs[64];

    int bh = blockIdx.x;
    int hh = bh & 7, b = bh >> 3;
    int t = threadIdx.x;
    int i0 = (t >> 4) * 4, j0 = (t & 15) * 4;

    for (int idx = t; idx < 4096; idx += 256) {
        float s = 0.f;
#pragma unroll
        for (int c = 0; c < NCH; c++) s += g_Mpart[((size_t)bh * NCH + c) * 4096 + idx];
        sA[idx] = s;
        sB[idx] = Wv[idx];
    }
    __syncthreads();

    float r16[4][4];

    // Stage 1: T[i,e] = sum_j M[i,j] Wv[e,j]
#pragma unroll
    for (int r = 0; r < 4; r++)
#pragma unroll
        for (int c = 0; c < 4; c++) r16[r][c] = 0.f;
    for (int j = 0; j < 64; j++) {
        float a[4], bv[4];
#pragma unroll
        for (int r = 0; r < 4; r++) a[r] = sA[(i0 + r) * 64 + j];
#pragma unroll
        for (int c = 0; c < 4; c++) bv[c] = sB[(j0 + c) * 64 + j];
#pragma unroll
        for (int r = 0; r < 4; r++)
#pragma unroll
            for (int c = 0; c < 4; c++) r16[r][c] += a[r] * bv[c];
    }
    __syncthreads();
#pragma unroll
    for (int r = 0; r < 4; r++)
#pragma unroll
        for (int c = 0; c < 4; c++) sA[(i0 + r) * 64 + j0 + c] = r16[r][c];
    for (int idx = t; idx < 4096; idx += 256) sB[idx] = Wk[idx];
    __syncthreads();

    // Stage 2: kv[d,e] = sum_i Wk[d,i] T[i,e]
#pragma unroll
    for (int r = 0; r < 4; r++)
#pragma unroll
        for (int c = 0; c < 4; c++) r16[r][c] = 0.f;
    for (int i = 0; i < 64; i++) {
        float a[4], bv[4];
#pragma unroll
        for (int r = 0; r < 4; r++) a[r] = sB[(i0 + r) * 64 + i];
#pragma unroll
        for (int c = 0; c < 4; c++) bv[c] = sA[i * 64 + j0 + c];
#pragma unroll
        for (int r = 0; r < 4; r++)
#pragma unroll
            for (int c = 0; c < 4; c++) r16[r][c] += a[r] * bv[c];
    }
    __syncthreads();
#pragma unroll
    for (int r = 0; r < 4; r++)
#pragma unroll
        for (int c = 0; c < 4; c++) sA[(i0 + r) * 64 + j0 + c] = r16[r][c];
    for (int idx = t; idx < 4096; idx += 256) sB[idx] = Wq[idx];
    __syncthreads();

    // Stage 3: rs[d] = gamma_h * (sum_e kv[d,e]^4)^(-1/4)
    {
        int w = t >> 5, lane = t & 31;
        float g = gamma[hh];
        for (int d = w * 8; d < w * 8 + 8; d++) {
            float x1 = sA[d * 64 + lane], x2 = sA[d * 64 + lane + 32];
            float p = (x1 * x1) * (x1 * x1) + (x2 * x2) * (x2 * x2);
#pragma unroll
            for (int o = 16; o > 0; o >>= 1) p += __shfl_xor_sync(0xffffffffu, p, o);
            if (lane == 0) rs[d] = g * rsqrtf(sqrtf(p));
        }
    }
    __syncthreads();
    for (int idx = t; idx < 4096; idx += 256) sA[idx] *= rs[idx >> 6];
    __syncthreads();

    // Stage 4: P[i,e] = sum_d Wq[d,i] kv_n[d,e]
#pragma unroll
    for (int r = 0; r < 4; r++)
#pragma unroll
        for (int c = 0; c < 4; c++) r16[r][c] = 0.f;
    for (int d = 0; d < 64; d++) {
        float a[4], bv[4];
#pragma unroll
        for (int r = 0; r < 4; r++) a[r] = sB[d * 64 + i0 + r];
#pragma unroll
        for (int c = 0; c < 4; c++) bv[c] = sA[d * 64 + j0 + c];
#pragma unroll
        for (int r = 0; r < 4; r++)
#pragma unroll
            for (int c = 0; c < 4; c++) r16[r][c] += a[r] * bv[c];
    }
    __syncthreads();
#pragma unroll
    for (int r = 0; r < 4; r++)
#pragma unroll
        for (int c = 0; c < 4; c++) sA[(i0 + r) * 64 + j0 + c] = r16[r][c];
    __syncthreads();

    // Stage 5: G[i,f] = sum_e P[i,e] Wo[f, h*64+e] -> Gt hi/lo
    for (int fb = 0; fb < 8; fb++) {
        for (int idx = t; idx < 4096; idx += 256) {
            int ff = idx >> 6, e = idx & 63;
            sB[idx] = Wo[(size_t)(fb * 64 + ff) * 512 + hh * 64 + e];
        }
        __syncthreads();
#pragma unroll
        for (int r = 0; r < 4; r++)
#pragma unroll
            for (int c = 0; c < 4; c++) r16[r][c] = 0.f;
        for (int e = 0; e < 64; e++) {
            float a[4], bv[4];
#pragma unroll
            for (int r = 0; r < 4; r++) a[r] = sA[(i0 + r) * 64 + e];
#pragma unroll
            for (int c = 0; c < 4; c++) bv[c] = sB[(j0 + c) * 64 + e];
#pragma unroll
            for (int r = 0; r < 4; r++)
#pragma unroll
                for (int c = 0; c < 4; c++) r16[r][c] += a[r] * bv[c];
        }
#pragma unroll
        for (int r = 0; r < 4; r++)
#pragma unroll
            for (int c = 0; c < 4; c++) {
                float val = r16[r][c];
                __nv_bfloat16 vh = __float2bfloat16(val);
                __nv_bfloat16 vl = __float2bfloat16(val - __bfloat162float(vh));
                size_t p = ((size_t)b * 512 + fb * 64 + j0 + c) * 512 + hh * 64 + i0 + r;
                g_Gt_hi[p] = vh;
                g_Gt_lo[p] = vl;
            }
        __syncthreads();
    }
}

// ---------------------------------------------------------------------------
// Kernel 3 (tensor): per block, 64 rows x all heads. Qp = q @ Wq^T per head
// via 3-pass split-bf16 mma; fused L4-norm reduction on fragments -> g_S.
// ---------------------------------------------------------------------------
__global__ __launch_bounds__(256) void k3_mma(const float* __restrict__ queries,
                                              const float* __restrict__ Wq,
                                              const float* __restrict__ gamma) {
    __shared__ __align__(16) char sm[49152];
    uint32_t sb = smem_u32(sm);
    int t = threadIdx.x, wid = t >> 5, lane = t & 31;
    size_t R0 = (size_t)blockIdx.x * 64;

    // --- convert Wq (fp32 [e][d]) -> bf16 hi/lo, swizzled ---
    {
        int row = t >> 2, c2 = t & 3;
        const float* src = Wq + row * 64 + c2 * 16;
        float4 v0 = *(const float4*)(src);
        float4 v1 = *(const float4*)(src + 4);
        float4 v2 = *(const float4*)(src + 8);
        float4 v3 = *(const float4*)(src + 12);
        uint4 h0, l0, h1, l1;
        conv8(v0, v1, 1.f, h0, l0);
        conv8(v2, v3, 1.f, h1, l1);
        uint32_t o0 = (uint32_t)row * 128 + (((2 * c2) ^ (row & 7)) * 16);
        uint32_t o1 = (uint32_t)row * 128 + (((2 * c2 + 1) ^ (row & 7)) * 16);
        *(uint4*)(sm + o0) = h0;
        *(uint4*)(sm + o1) = h1;
        *(uint4*)(sm + 8192 + o0) = l0;
        *(uint4*)(sm + 8192 + o1) = l1;
    }

    int hsel = wid >> 2, mtile = wid & 3;
    int lrA = (lane & 7) + (lane & 8);
    int lcA = (lane >> 4) & 1;
    int lrB = (lane & 7) + ((lane >> 4) & 1) * 8;
    int lcB = (lane >> 3) & 1;
    int arow = mtile * 16 + lrA;
    uint32_t qbase = 16384u + (uint32_t)hsel * 16384u;
    uint32_t aoff_row = qbase + (uint32_t)arow * 128;
    int asw = arow & 7;

    for (int hp = 0; hp < 4; hp++) {
        __syncthreads();
        {
            int row = t >> 2, c2 = t & 3;
#pragma unroll
            for (int hs = 0; hs < 2; hs++) {
                int h = 2 * hp + hs;
                const float* src = queries + (R0 + row) * 512 + h * 64 + c2 * 16;
                float4 v0 = *(const float4*)(src);
                float4 v1 = *(const float4*)(src + 4);
                float4 v2 = *(const float4*)(src + 8);
                float4 v3 = *(const float4*)(src + 12);
                uint4 h0, l0, h1, l1;
                conv8(v0, v1, 1.f, h0, l0);
                conv8(v2, v3, 1.f, h1, l1);
                uint32_t qb = 16384u + (uint32_t)hs * 16384u;
                uint32_t o0 = qb + (uint32_t)row * 128 + (((2 * c2) ^ (row & 7)) * 16);
                uint32_t o1 = qb + (uint32_t)row * 128 + (((2 * c2 + 1) ^ (row & 7)) * 16);
                *(uint4*)(sm + o0) = h0;
                *(uint4*)(sm + o1) = h1;
                *(uint4*)(sm + 8192 + o0) = l0;
                *(uint4*)(sm + 8192 + o1) = l1;
            }
        }
        __syncthreads();

        int h = 2 * hp + hsel;
        float acc[8][4];
#pragma unroll
        for (int j = 0; j < 8; j++)
#pragma unroll
            for (int r = 0; r < 4; r++) acc[j][r] = 0.f;

#pragma unroll
        for (int k16 = 0; k16 < 4; k16++) {
            uint32_t ah[4], al[4];
            uint32_t ao = aoff_row + (((k16 * 2 + lcA) ^ asw) * 16);
            ldsm4(ah, sb + ao);
            ldsm4(al, sb + 8192 + ao);
#pragma unroll
            for (int p = 0; p < 4; p++) {
                int brow = p * 16 + lrB;
                uint32_t bo = (uint32_t)brow * 128 + (((k16 * 2 + lcB) ^ (brow & 7)) * 16);
                uint32_t bh4[4], bl4[4];
                ldsm4(bh4, sb + bo);
                ldsm4(bl4, sb + 8192 + bo);
#pragma unroll
                for (int j = 0; j < 2; j++) {
                    mma16816(acc[p * 2 + j], ah, &bh4[j * 2]);
                    mma16816(acc[p * 2 + j], ah, &bl4[j * 2]);
                    mma16816(acc[p * 2 + j], al, &bh4[j * 2]);
                }
            }
        }

        float p0 = 0.f, p1 = 0.f;
#pragma unroll
        for (int j = 0; j < 8; j++) {
            float a0 = acc[j][0], a1 = acc[j][1];
            float a2 = acc[j][2], a3 = acc[j][3];
            p0 += (a0 * a0) * (a0 * a0) + (a1 * a1) * (a1 * a1);
            p1 += (a2 * a2) * (a2 * a2) + (a3 * a3) * (a3 * a3);
        }
#pragma unroll
        for (int o = 1; o <= 2; o <<= 1) {
            p0 += __shfl_xor_sync(0xffffffffu, p0, o);
            p1 += __shfl_xor_sync(0xffffffffu, p1, o);
        }
        if ((lane & 3) == 0) {
            float gm = __ldg(&gamma[h]);
            size_t row0 = R0 + mtile * 16 + (lane >> 2);
            g_S[row0 * CH + h] = gm * rsqrtf(sqrtf(p0));
            g_S[(row0 + 8) * CH + h] = gm * rsqrtf(sqrtf(p1));
        }
    }
}

// ---------------------------------------------------------------------------
// Kernel 4: warp-mma bf16 3-pass GEMM. CTA tile M=128, N=256, K=512.
// 16 warps (4m x 4n), warp tile 32x64. K=64 per stage (one head), double-
// buffered 192KB dynamic smem, cp.async B, in-loop A fp32->bf16 hi/lo.
// Grid (2, 64, 8) x 512 threads.
// Stage layout (98304 B): Ahi[0,16K) Alo[16K,32K) Bhi[32K,64K) Blo[64K,96K)
// Rows are 128B (64 bf16); swizzle chunk^(row&7) on 16B chunks.
// ---------------------------------------------------------------------------
constexpr int K4_STAGE = 98304;
constexpr int K4_SMEM = 2 * K4_STAGE;   // 196608

__global__ void __launch_bounds__(512) k4_mma(const float* __restrict__ queries,
                                              const float* __restrict__ bo,
                                              float* __restrict__ out) {
    extern __shared__ __align__(16) char smem[];
    uint32_t sbase = smem_u32(smem);

    int b = blockIdx.z, mt = blockIdx.y, nb = blockIdx.x;
    int t = threadIdx.x, wid = t >> 5, lane = t & 31;
    int wm = wid >> 2, wn = wid & 3;
    size_t rowbase = (size_t)b * CL + (size_t)mt * 128;
    int f0 = nb * 256;

    // A conversion role: row = t>>2 (0..127), quarter aq4 = t&3 (16 k-values)
    int arow = t >> 2, aq4 = t & 3;
    const float* asrc = queries + (rowbase + arow) * 512 + aq4 * 16;
    const float* srow = g_S + (rowbase + arow) * 8;
    uint32_t aswz = (uint32_t)(arow & 7);
    uint32_t ao0 = (uint32_t)arow * 128 + ((((uint32_t)(2 * aq4)) ^ aswz) * 16);
    uint32_t ao1 = (uint32_t)arow * 128 + ((((uint32_t)(2 * aq4 + 1)) ^ aswz) * 16);

    // B copy role: row brow = t>>1 (0..255), half bhalf = t&1 (4 x 16B chunks)
    int brow = t >> 1, bhalf = t & 1;
    const __nv_bfloat16* bhsrc = g_Gt_hi + ((size_t)(b * 512 + f0 + brow)) * 512;
    const __nv_bfloat16* blsrc = g_Gt_lo + ((size_t)(b * 512 + f0 + brow)) * 512;
    uint32_t bswz = (uint32_t)(brow & 7);
    uint32_t brow_off = 32768u + (uint32_t)brow * 128;

    // ldmatrix per-lane offsets
    int lrA = (lane & 7) + (lane & 8);
    int lcA = (lane >> 4) & 1;
    uint32_t amo[2]; uint32_t amsw[2];
#pragma unroll
    for (int m2 = 0; m2 < 2; m2++) {
        int row = wm * 32 + m2 * 16 + lrA;
        amo[m2] = (uint32_t)row * 128;
        amsw[m2] = (uint32_t)(row & 7);
    }
    int lrB = (lane & 7) + ((lane >> 4) & 1) * 8;
    int lcB = (lane >> 3) & 1;
    uint32_t bro[4]; uint32_t brsw[4];
#pragma unroll
    for (int p = 0; p < 4; p++) {
        int row = wn * 64 + p * 16 + lrB;
        bro[p] = 32768u + (uint32_t)row * 128;
        brsw[p] = (uint32_t)(row & 7);
    }

    float acc[2][8][4];
#pragma unroll
    for (int m2 = 0; m2 < 2; m2++)
#pragma unroll
        for (int nt = 0; nt < 8; nt++)
#pragma unroll
            for (int r = 0; r < 4; r++) acc[m2][nt][r] = 0.f;

    // ---- prologue: stage 0 (head 0) ----
    {
#pragma unroll
        for (int i = 0; i < 4; i++) {
            uint32_t chunk = (uint32_t)(bhalf * 4 + i);
            uint32_t dst = brow_off + ((chunk ^ bswz) * 16);
            cp16(sbase + dst, bhsrc + chunk * 8);
            cp16(sbase + dst + 32768u, blsrc + chunk * 8);
        }
        CP_COMMIT();
        float sc = __ldg(srow);
        float4 v0 = *(const float4*)(asrc);
        float4 v1 = *(const float4*)(asrc + 4);
        float4 v2 = *(const float4*)(asrc + 8);
        float4 v3 = *(const float4*)(asrc + 12);
        uint4 h0, l0, h1, l1;
        conv8(v0, v1, sc, h0, l0);
        conv8(v2, v3, sc, h1, l1);
        *(uint4*)(smem + ao0) = h0;
        *(uint4*)(smem + ao1) = h1;
        *(uint4*)(smem + 16384 + ao0) = l0;
        *(uint4*)(smem + 16384 + ao1) = l1;
    }

    for (int c = 0; c < 8; c++) {
        int s = c & 1;
        uint32_t stg = sbase + s * K4_STAGE;

        CP_WAIT(0);
        __syncthreads();

        float4 v0, v1, v2, v3;
        float psc = 0.f;
        if (c < 7) {
            uint32_t nst = sbase + (s ^ 1) * K4_STAGE;
#pragma unroll
            for (int i = 0; i < 4; i++) {
                uint32_t chunk = (uint32_t)(bhalf * 4 + i);
                uint32_t dst = brow_off + ((chunk ^ bswz) * 16);
                cp16(nst + dst, bhsrc + (c + 1) * 64 + chunk * 8);
                cp16(nst + dst + 32768u, blsrc + (c + 1) * 64 + chunk * 8);
            }
            CP_COMMIT();
            psc = __ldg(srow + c + 1);
            const float* ap = asrc + (c + 1) * 64;
            v0 = *(const float4*)(ap);
            v1 = *(const float4*)(ap + 4);
            v2 = *(const float4*)(ap + 8);
            v3 = *(const float4*)(ap + 12);
        }

#pragma unroll
        for (int k16 = 0; k16 < 4; k16++) {
            uint32_t ah[2][4], al[2][4];
#pragma unroll
            for (int m2 = 0; m2 < 2; m2++) {
                uint32_t ao = stg + amo[m2]
                            + ((((uint32_t)(k16 * 2) + lcA) ^ amsw[m2]) * 16);
                ldsm4(ah[m2], ao);
                ldsm4(al[m2], ao + 16384u);
            }
#pragma unroll
            for (int p = 0; p < 4; p++) {
                uint32_t bof = stg + bro[p]
                             + ((((uint32_t)(k16 * 2) + lcB) ^ brsw[p]) * 16);
                uint32_t bh4[4], bl4[4];
                ldsm4(bh4, bof);
                ldsm4(bl4, bof + 32768u);
#pragma unroll
                for (int j = 0; j < 2; j++)
#pragma unroll
                    for (int m2 = 0; m2 < 2; m2++)
                        mma16816(acc[m2][p * 2 + j], ah[m2], &bh4[j * 2]);
#pragma unroll
                for (int j = 0; j < 2; j++)
#pragma unroll
                    for (int m2 = 0; m2 < 2; m2++)
                        mma16816(acc[m2][p * 2 + j], ah[m2], &bl4[j * 2]);
#pragma unroll
                for (int j = 0; j < 2; j++)
#pragma unroll
                    for (int m2 = 0; m2 < 2; m2++)
                        mma16816(acc[m2][p * 2 + j], al[m2], &bh4[j * 2]);
            }
        }

        if (c < 7) {
            uint4 h0, l0, h1, l1;
            conv8(v0, v1, psc, h0, l0);
            conv8(v2, v3, psc, h1, l1);
            char* np = smem + (s ^ 1) * K4_STAGE;
            *(uint4*)(np + ao0) = h0;
            *(uint4*)(np + ao1) = h1;
            *(uint4*)(np + 16384 + ao0) = l0;
            *(uint4*)(np + 16384 + ao1) = l1;
        }
    }

    // epilogue: add bias, write fp32
    int r0 = lane >> 2, cbase = 2 * (lane & 3);
#pragma unroll
    for (int m2 = 0; m2 < 2; m2++) {
        size_t row = rowbase + wm * 32 + m2 * 16 + r0;
        float* orow0 = out + row * 512 + f0 + wn * 64;
        float* orow1 = orow0 + (size_t)8 * 512;
        const float* bp = bo + f0 + wn * 64;
#pragma unroll
        for (int nt = 0; nt < 8; nt++) {
            int col = nt * 8 + cbase;
            float b0v = bp[col], b1v = bp[col + 1];
            float2 v0 = make_float2(acc[m2][nt][0] + b0v, acc[m2][nt][1] + b1v);
            float2 v1 = make_float2(acc[m2][nt][2] + b0v, acc[m2][nt][3] + b1v);
            *(float2*)(orow0 + col) = v0;
            *(float2*)(orow1 + col) = v1;
        }
    }
}

// ---------------------------------------------------------------------------
extern "C" void kernel_launch(void* const* d_in, const int* in_sizes, int n_in,
                              void* d_out, int out_size) {
    const float* queries = (const float*)d_in[0];
    const float* keys    = (const float*)d_in[1];
    const float* values  = (const float*)d_in[2];
    const float* Wq      = (const float*)d_in[3];
    const float* Wk      = (const float*)d_in[4];
    const float* Wv      = (const float*)d_in[5];
    const float* Wo      = (const float*)d_in[6];
    const float* bo      = (const float*)d_in[7];
    const float* gamma   = (const float*)d_in[8];
    float* out = (float*)d_out;

    cudaFuncSetAttribute(k4_mma, cudaFuncAttributeMaxDynamicSharedMemorySize, K4_SMEM);

    k1_moment<<<CB * CH * NCH, 256>>>(keys, values);
    k2_prepG<<<CB * CH, 256>>>(Wq, Wk, Wv, Wo, gamma);
    k3_mma<<<CB * CL / 64, 256>>>(queries, Wq, gamma);
    k4_mma<<<dim3(2, CL / 128, CB), 512, K4_SMEM>>>(queries, bo, out);
}

// round 17
// speedup vs baseline: 2.2144x; 1.1318x over previous
#include <cuda_runtime.h>
#include <cuda_bf16.h>
#include <cstdint>

// ---------------------------------------------------------------------------
// UFOAttention restructured:
//   M[b,h]  = sum_l outer(k_raw[b,l,h,:], v_raw[b,l,h,:])            (k1)
//   kv = Wk M Wv^T ; kv_n = xnorm ; P = Wq^T kv_n ; G = P Wo_h^T ;
//   Gt (transposed, split to bf16 hi/lo)                              (k2, fb-split)
//   s[b,l,h] = gamma_h / ||q_raw[b,l,h,:] Wq^T||_4  (mma 3-pass)      (k3)
//   out[b]  = diag(s)*Q_raw @ Gbig + bo  via mma.sync bf16 3-pass     (k4)
// Plain sm_103-legal instructions only (no tcgen05 — target lacks 'a').
// ---------------------------------------------------------------------------

constexpr int CB = 8;
constexpr int CL = 8192;
constexpr int CH = 8;
constexpr int CD = 64;
constexpr int CE = 512;
constexpr int NCH = 16;
constexpr int CHUNK = CL / NCH;   // 512

__device__ float g_Mpart[CB * CH * NCH * CD * CD];
__device__ float g_S[CB * CL * CH];
__device__ __nv_bfloat16 g_Gt_hi[CB * CE * CE];   // [b][f][k]
__device__ __nv_bfloat16 g_Gt_lo[CB * CE * CE];

typedef unsigned long long u64;

__device__ __forceinline__ u64 pack2(float a, float b) {
    u64 r; asm("mov.b64 %0, {%1,%2};" : "=l"(r) : "f"(a), "f"(b)); return r;
}
__device__ __forceinline__ void unpack2(u64 v, float& a, float& b) {
    asm("mov.b64 {%0,%1}, %2;" : "=f"(a), "=f"(b) : "l"(v));
}
__device__ __forceinline__ u64 fma2(u64 a, u64 b, u64 c) {
    u64 d; asm("fma.rn.f32x2 %0, %1, %2, %3;" : "=l"(d) : "l"(a), "l"(b), "l"(c)); return d;
}
__device__ __forceinline__ uint32_t smem_u32(const void* p) {
    uint32_t a;
    asm("{ .reg .u64 t; cvta.to.shared.u64 t, %1; cvt.u32.u64 %0, t; }" : "=r"(a) : "l"(p));
    return a;
}
#define CP_COMMIT() asm volatile("cp.async.commit_group;" ::: "memory")
#define CP_WAIT(n)  asm volatile("cp.async.wait_group %0;" :: "n"(n) : "memory")
__device__ __forceinline__ void cp16(uint32_t dst, const void* src) {
    asm volatile("cp.async.ca.shared.global [%0], [%1], 16;" :: "r"(dst), "l"(src) : "memory");
}
__device__ __forceinline__ void ldsm4(uint32_t* r, uint32_t a) {
    asm volatile("ldmatrix.sync.aligned.m8n8.x4.shared.b16 {%0,%1,%2,%3}, [%4];"
                 : "=r"(r[0]), "=r"(r[1]), "=r"(r[2]), "=r"(r[3]) : "r"(a));
}
__device__ __forceinline__ void mma16816(float* c, const uint32_t* a, const uint32_t* b) {
    asm volatile("mma.sync.aligned.m16n8k16.row.col.f32.bf16.bf16.f32 "
                 "{%0,%1,%2,%3}, {%4,%5,%6,%7}, {%8,%9}, {%0,%1,%2,%3};"
                 : "+f"(c[0]), "+f"(c[1]), "+f"(c[2]), "+f"(c[3])
                 : "r"(a[0]), "r"(a[1]), "r"(a[2]), "r"(a[3]), "r"(b[0]), "r"(b[1]));
}
__device__ __forceinline__ uint32_t pack_bf(__nv_bfloat16 a, __nv_bfloat16 b) {
    unsigned short x = *(unsigned short*)&a, y = *(unsigned short*)&b;
    return (uint32_t)x | ((uint32_t)y << 16);
}
// convert 8 scaled floats -> 8 bf16 hi (uint4) + 8 bf16 lo (uint4)
__device__ __forceinline__ void conv8(float4 v0, float4 v1, float sc,
                                      uint4& hi, uint4& lo) {
    float x[8] = {v0.x * sc, v0.y * sc, v0.z * sc, v0.w * sc,
                  v1.x * sc, v1.y * sc, v1.z * sc, v1.w * sc};
    __nv_bfloat16 h[8], l[8];
#pragma unroll
    for (int i = 0; i < 8; i++) {
        h[i] = __float2bfloat16(x[i]);
        l[i] = __float2bfloat16(x[i] - __bfloat162float(h[i]));
    }
    hi = make_uint4(pack_bf(h[0], h[1]), pack_bf(h[2], h[3]),
                    pack_bf(h[4], h[5]), pack_bf(h[6], h[7]));
    lo = make_uint4(pack_bf(l[0], l[1]), pack_bf(l[2], l[3]),
                    pack_bf(l[4], l[5]), pack_bf(l[6], l[7]));
}

// ---------------------------------------------------------------------------
// Kernel 1: partial raw moments, 3-stage cp.async pipeline, 16 rows/stage.
// ---------------------------------------------------------------------------
__global__ __launch_bounds__(256) void k1_moment(const float* __restrict__ keys,
                                                 const float* __restrict__ values) {
    constexpr int RS = 16;
    constexpr int NIT = CHUNK / RS;   // 32
    __shared__ __align__(16) float sk[3][RS][64];
    __shared__ __align__(16) float sv[3][RS][64];

    int blk = blockIdx.x;
    int chunk = blk % NCH;
    int bh = blk / NCH;
    int hh = bh % CH, b = bh / CH;
    int t = threadIdx.x;
    int ti = t >> 4, tj = t & 15;
    int crow = t >> 4, cc = t & 15;

    const float* kb = keys   + (size_t)b * CL * CE + hh * CD;
    const float* vb = values + (size_t)b * CL * CE + hh * CD;
    int l0 = chunk * CHUNK;

    u64 acc[4][2];
#pragma unroll
    for (int r = 0; r < 4; r++) { acc[r][0] = 0ull; acc[r][1] = 0ull; }

#pragma unroll
    for (int pit = 0; pit < 2; pit++) {
        size_t l = (size_t)(l0 + pit * RS + crow);
        cp16(smem_u32(&sk[pit][crow][cc * 4]), kb + l * CE + cc * 4);
        cp16(smem_u32(&sv[pit][crow][cc * 4]), vb + l * CE + cc * 4);
        CP_COMMIT();
    }

    for (int it = 0; it < NIT; it++) {
        int s = it % 3;
        if (it < NIT - 1) CP_WAIT(1); else CP_WAIT(0);
        __syncthreads();
        if (it + 2 < NIT) {
            int ns = (it + 2) % 3;
            size_t l = (size_t)(l0 + (it + 2) * RS + crow);
            cp16(smem_u32(&sk[ns][crow][cc * 4]), kb + l * CE + cc * 4);
            cp16(smem_u32(&sv[ns][crow][cc * 4]), vb + l * CE + cc * 4);
            CP_COMMIT();
        }
#pragma unroll
        for (int r = 0; r < RS; r++) {
            u64 kk[4];
#pragma unroll
            for (int rr = 0; rr < 4; rr++) {
                float kv_ = sk[s][r][4 * ti + rr];
                kk[rr] = pack2(kv_, kv_);
            }
            u64 v0 = *(const u64*)&sv[s][r][4 * tj];
            u64 v1 = *(const u64*)&sv[s][r][4 * tj + 2];
#pragma unroll
            for (int rr = 0; rr < 4; rr++) {
                acc[rr][0] = fma2(kk[rr], v0, acc[rr][0]);
                acc[rr][1] = fma2(kk[rr], v1, acc[rr][1]);
            }
        }
    }

    float* Mp = g_Mpart + ((size_t)bh * NCH + chunk) * (CD * CD);
#pragma unroll
    for (int r = 0; r < 4; r++) {
        float a, bv, c, dv;
        unpack2(acc[r][0], a, bv);
        unpack2(acc[r][1], c, dv);
        int row = 4 * ti + r;
        Mp[row * 64 + 4 * tj + 0] = a;
        Mp[row * 64 + 4 * tj + 1] = bv;
        Mp[row * 64 + 4 * tj + 2] = c;
        Mp[row * 64 + 4 * tj + 3] = dv;
    }
}

// ---------------------------------------------------------------------------
// Kernel 2: per (b,h,fb): redo cheap stages 1-4, then ONE fb block of stage 5.
// Grid 512 blocks (bh = blk>>3, fb = blk&7) x 256 threads.
// ---------------------------------------------------------------------------
__global__ __launch_bounds__(256) void k2_prepG(const float* __restrict__ Wq,
                                                const float* __restrict__ Wk,
                                                const float* __restrict__ Wv,
                                                const float* __restrict__ Wo,
                                                const float* __restrict__ gamma) {
    __shared__ float sA[4096];
    __shared__ float sB[4096];
    __shared__ float rs[64];

    int blk = blockIdx.x;
    int bh = blk >> 3, fb = blk & 7;
    int hh = bh & 7, b = bh >> 3;
    int t = threadIdx.x;
    int i0 = (t >> 4) * 4, j0 = (t & 15) * 4;

    for (int idx = t; idx < 4096; idx += 256) {
        float s = 0.f;
#pragma unroll
        for (int c = 0; c < NCH; c++) s += g_Mpart[((size_t)bh * NCH + c) * 4096 + idx];
        sA[idx] = s;
        sB[idx] = Wv[idx];
    }
    __syncthreads();

    float r16[4][4];

    // Stage 1: T[i,e] = sum_j M[i,j] Wv[e,j]
#pragma unroll
    for (int r = 0; r < 4; r++)
#pragma unroll
        for (int c = 0; c < 4; c++) r16[r][c] = 0.f;
    for (int j = 0; j < 64; j++) {
        float a[4], bv[4];
#pragma unroll
        for (int r = 0; r < 4; r++) a[r] = sA[(i0 + r) * 64 + j];
#pragma unroll
        for (int c = 0; c < 4; c++) bv[c] = sB[(j0 + c) * 64 + j];
#pragma unroll
        for (int r = 0; r < 4; r++)
#pragma unroll
            for (int c = 0; c < 4; c++) r16[r][c] += a[r] * bv[c];
    }
    __syncthreads();
#pragma unroll
    for (int r = 0; r < 4; r++)
#pragma unroll
        for (int c = 0; c < 4; c++) sA[(i0 + r) * 64 + j0 + c] = r16[r][c];
    for (int idx = t; idx < 4096; idx += 256) sB[idx] = Wk[idx];
    __syncthreads();

    // Stage 2: kv[d,e] = sum_i Wk[d,i] T[i,e]
#pragma unroll
    for (int r = 0; r < 4; r++)
#pragma unroll
        for (int c = 0; c < 4; c++) r16[r][c] = 0.f;
    for (int i = 0; i < 64; i++) {
        float a[4], bv[4];
#pragma unroll
        for (int r = 0; r < 4; r++) a[r] = sB[(i0 + r) * 64 + i];
#pragma unroll
        for (int c = 0; c < 4; c++) bv[c] = sA[i * 64 + j0 + c];
#pragma unroll
        for (int r = 0; r < 4; r++)
#pragma unroll
            for (int c = 0; c < 4; c++) r16[r][c] += a[r] * bv[c];
    }
    __syncthreads();
#pragma unroll
    for (int r = 0; r < 4; r++)
#pragma unroll
        for (int c = 0; c < 4; c++) sA[(i0 + r) * 64 + j0 + c] = r16[r][c];
    for (int idx = t; idx < 4096; idx += 256) sB[idx] = Wq[idx];
    __syncthreads();

    // Stage 3: rs[d] = gamma_h * (sum_e kv[d,e]^4)^(-1/4)
    {
        int w = t >> 5, lane = t & 31;
        float g = gamma[hh];
        for (int d = w * 8; d < w * 8 + 8; d++) {
            float x1 = sA[d * 64 + lane], x2 = sA[d * 64 + lane + 32];
            float p = (x1 * x1) * (x1 * x1) + (x2 * x2) * (x2 * x2);
#pragma unroll
            for (int o = 16; o > 0; o >>= 1) p += __shfl_xor_sync(0xffffffffu, p, o);
            if (lane == 0) rs[d] = g * rsqrtf(sqrtf(p));
        }
    }
    __syncthreads();
    for (int idx = t; idx < 4096; idx += 256) sA[idx] *= rs[idx >> 6];
    __syncthreads();

    // Stage 4: P[i,e] = sum_d Wq[d,i] kv_n[d,e]
#pragma unroll
    for (int r = 0; r < 4; r++)
#pragma unroll
        for (int c = 0; c < 4; c++) r16[r][c] = 0.f;
    for (int d = 0; d < 64; d++) {
        float a[4], bv[4];
#pragma unroll
        for (int r = 0; r < 4; r++) a[r] = sB[d * 64 + i0 + r];
#pragma unroll
        for (int c = 0; c < 4; c++) bv[c] = sA[d * 64 + j0 + c];
#pragma unroll
        for (int r = 0; r < 4; r++)
#pragma unroll
            for (int c = 0; c < 4; c++) r16[r][c] += a[r] * bv[c];
    }
    __syncthreads();
#pragma unroll
    for (int r = 0; r < 4; r++)
#pragma unroll
        for (int c = 0; c < 4; c++) sA[(i0 + r) * 64 + j0 + c] = r16[r][c];
    __syncthreads();

    // Stage 5 (this block's fb only): G[i,f] = sum_e P[i,e] Wo[f, h*64+e]
    {
        for (int idx = t; idx < 4096; idx += 256) {
            int ff = idx >> 6, e = idx & 63;
            sB[idx] = Wo[(size_t)(fb * 64 + ff) * 512 + hh * 64 + e];
        }
        __syncthreads();
#pragma unroll
        for (int r = 0; r < 4; r++)
#pragma unroll
            for (int c = 0; c < 4; c++) r16[r][c] = 0.f;
        for (int e = 0; e < 64; e++) {
            float a[4], bv[4];
#pragma unroll
            for (int r = 0; r < 4; r++) a[r] = sA[(i0 + r) * 64 + e];
#pragma unroll
            for (int c = 0; c < 4; c++) bv[c] = sB[(j0 + c) * 64 + e];
#pragma unroll
            for (int r = 0; r < 4; r++)
#pragma unroll
                for (int c = 0; c < 4; c++) r16[r][c] += a[r] * bv[c];
        }
#pragma unroll
        for (int r = 0; r < 4; r++)
#pragma unroll
            for (int c = 0; c < 4; c++) {
                float val = r16[r][c];
                __nv_bfloat16 vh = __float2bfloat16(val);
                __nv_bfloat16 vl = __float2bfloat16(val - __bfloat162float(vh));
                size_t p = ((size_t)b * 512 + fb * 64 + j0 + c) * 512 + hh * 64 + i0 + r;
                g_Gt_hi[p] = vh;
                g_Gt_lo[p] = vl;
            }
    }
}

// ---------------------------------------------------------------------------
// Kernel 3 (tensor): per block, 64 rows x all heads. Qp = q @ Wq^T per head
// via 3-pass split-bf16 mma; fused L4-norm reduction on fragments -> g_S.
// ---------------------------------------------------------------------------
__global__ __launch_bounds__(256) void k3_mma(const float* __restrict__ queries,
                                              const float* __restrict__ Wq,
                                              const float* __restrict__ gamma) {
    __shared__ __align__(16) char sm[49152];
    uint32_t sb = smem_u32(sm);
    int t = threadIdx.x, wid = t >> 5, lane = t & 31;
    size_t R0 = (size_t)blockIdx.x * 64;

    // --- convert Wq (fp32 [e][d]) -> bf16 hi/lo, swizzled ---
    {
        int row = t >> 2, c2 = t & 3;
        const float* src = Wq + row * 64 + c2 * 16;
        float4 v0 = *(const float4*)(src);
        float4 v1 = *(const float4*)(src + 4);
        float4 v2 = *(const float4*)(src + 8);
        float4 v3 = *(const float4*)(src + 12);
        uint4 h0, l0, h1, l1;
        conv8(v0, v1, 1.f, h0, l0);
        conv8(v2, v3, 1.f, h1, l1);
        uint32_t o0 = (uint32_t)row * 128 + (((2 * c2) ^ (row & 7)) * 16);
        uint32_t o1 = (uint32_t)row * 128 + (((2 * c2 + 1) ^ (row & 7)) * 16);
        *(uint4*)(sm + o0) = h0;
        *(uint4*)(sm + o1) = h1;
        *(uint4*)(sm + 8192 + o0) = l0;
        *(uint4*)(sm + 8192 + o1) = l1;
    }

    int hsel = wid >> 2, mtile = wid & 3;
    int lrA = (lane & 7) + (lane & 8);
    int lcA = (lane >> 4) & 1;
    int lrB = (lane & 7) + ((lane >> 4) & 1) * 8;
    int lcB = (lane >> 3) & 1;
    int arow = mtile * 16 + lrA;
    uint32_t qbase = 16384u + (uint32_t)hsel * 16384u;
    uint32_t aoff_row = qbase + (uint32_t)arow * 128;
    int asw = arow & 7;

    for (int hp = 0; hp < 4; hp++) {
        __syncthreads();
        {
            int row = t >> 2, c2 = t & 3;
#pragma unroll
            for (int hs = 0; hs < 2; hs++) {
                int h = 2 * hp + hs;
                const float* src = queries + (R0 + row) * 512 + h * 64 + c2 * 16;
                float4 v0 = *(const float4*)(src);
                float4 v1 = *(const float4*)(src + 4);
                float4 v2 = *(const float4*)(src + 8);
                float4 v3 = *(const float4*)(src + 12);
                uint4 h0, l0, h1, l1;
                conv8(v0, v1, 1.f, h0, l0);
                conv8(v2, v3, 1.f, h1, l1);
                uint32_t qb = 16384u + (uint32_t)hs * 16384u;
                uint32_t o0 = qb + (uint32_t)row * 128 + (((2 * c2) ^ (row & 7)) * 16);
                uint32_t o1 = qb + (uint32_t)row * 128 + (((2 * c2 + 1) ^ (row & 7)) * 16);
                *(uint4*)(sm + o0) = h0;
                *(uint4*)(sm + o1) = h1;
                *(uint4*)(sm + 8192 + o0) = l0;
                *(uint4*)(sm + 8192 + o1) = l1;
            }
        }
        __syncthreads();

        int h = 2 * hp + hsel;
        float acc[8][4];
#pragma unroll
        for (int j = 0; j < 8; j++)
#pragma unroll
            for (int r = 0; r < 4; r++) acc[j][r] = 0.f;

#pragma unroll
        for (int k16 = 0; k16 < 4; k16++) {
            uint32_t ah[4], al[4];
            uint32_t ao = aoff_row + (((k16 * 2 + lcA) ^ asw) * 16);
            ldsm4(ah, sb + ao);
            ldsm4(al, sb + 8192 + ao);
#pragma unroll
            for (int p = 0; p < 4; p++) {
                int brow = p * 16 + lrB;
                uint32_t bo = (uint32_t)brow * 128 + (((k16 * 2 + lcB) ^ (brow & 7)) * 16);
                uint32_t bh4[4], bl4[4];
                ldsm4(bh4, sb + bo);
                ldsm4(bl4, sb + 8192 + bo);
#pragma unroll
                for (int j = 0; j < 2; j++) {
                    mma16816(acc[p * 2 + j], ah, &bh4[j * 2]);
                    mma16816(acc[p * 2 + j], ah, &bl4[j * 2]);
                    mma16816(acc[p * 2 + j], al, &bh4[j * 2]);
                }
            }
        }

        float p0 = 0.f, p1 = 0.f;
#pragma unroll
        for (int j = 0; j < 8; j++) {
            float a0 = acc[j][0], a1 = acc[j][1];
            float a2 = acc[j][2], a3 = acc[j][3];
            p0 += (a0 * a0) * (a0 * a0) + (a1 * a1) * (a1 * a1);
            p1 += (a2 * a2) * (a2 * a2) + (a3 * a3) * (a3 * a3);
        }
#pragma unroll
        for (int o = 1; o <= 2; o <<= 1) {
            p0 += __shfl_xor_sync(0xffffffffu, p0, o);
            p1 += __shfl_xor_sync(0xffffffffu, p1, o);
        }
        if ((lane & 3) == 0) {
            float gm = __ldg(&gamma[h]);
            size_t row0 = R0 + mtile * 16 + (lane >> 2);
            g_S[row0 * CH + h] = gm * rsqrtf(sqrtf(p0));
            g_S[(row0 + 8) * CH + h] = gm * rsqrtf(sqrtf(p1));
        }
    }
}

// ---------------------------------------------------------------------------
// Kernel 4: warp-mma bf16 3-pass GEMM. CTA tile M=128, N=256, K=512.
// 16 warps (4m x 4n), warp tile 32x64. K=64 per stage, double-buffered 192KB
// smem. Intra-warp fragment double-buffering: next fragments prefetched
// BEFORE current 12 MMAs so ldsm latency hides under tensor ops.
// Grid (2, 64, 8) x 512 threads.
// Stage layout (98304 B): Ahi[0,16K) Alo[16K,32K) Bhi[32K,64K) Blo[64K,96K)
// ---------------------------------------------------------------------------
constexpr int K4_STAGE = 98304;
constexpr int K4_SMEM = 2 * K4_STAGE;   // 196608

__global__ void __launch_bounds__(512) k4_mma(const float* __restrict__ queries,
                                              const float* __restrict__ bo,
                                              float* __restrict__ out) {
    extern __shared__ __align__(16) char smem[];
    uint32_t sbase = smem_u32(smem);

    int b = blockIdx.z, mt = blockIdx.y, nb = blockIdx.x;
    int t = threadIdx.x, wid = t >> 5, lane = t & 31;
    int wm = wid >> 2, wn = wid & 3;
    size_t rowbase = (size_t)b * CL + (size_t)mt * 128;
    int f0 = nb * 256;

    // A conversion role: row = t>>2 (0..127), quarter aq4 = t&3 (16 k-values)
    int arow = t >> 2, aq4 = t & 3;
    const float* asrc = queries + (rowbase + arow) * 512 + aq4 * 16;
    const float* srow = g_S + (rowbase + arow) * 8;
    uint32_t aswz = (uint32_t)(arow & 7);
    uint32_t ao0 = (uint32_t)arow * 128 + ((((uint32_t)(2 * aq4)) ^ aswz) * 16);
    uint32_t ao1 = (uint32_t)arow * 128 + ((((uint32_t)(2 * aq4 + 1)) ^ aswz) * 16);

    // B copy role: row brow = t>>1 (0..255), half bhalf = t&1 (4 x 16B chunks)
    int brow = t >> 1, bhalf = t & 1;
    const __nv_bfloat16* bhsrc = g_Gt_hi + ((size_t)(b * 512 + f0 + brow)) * 512;
    const __nv_bfloat16* blsrc = g_Gt_lo + ((size_t)(b * 512 + f0 + brow)) * 512;
    uint32_t bswz = (uint32_t)(brow & 7);
    uint32_t brow_off = 32768u + (uint32_t)brow * 128;

    // ldmatrix per-lane offsets
    int lrA = (lane & 7) + (lane & 8);
    int lcA = (lane >> 4) & 1;
    uint32_t amo[2]; uint32_t amsw[2];
#pragma unroll
    for (int m2 = 0; m2 < 2; m2++) {
        int row = wm * 32 + m2 * 16 + lrA;
        amo[m2] = (uint32_t)row * 128;
        amsw[m2] = (uint32_t)(row & 7);
    }
    int lrB = (lane & 7) + ((lane >> 4) & 1) * 8;
    int lcB = (lane >> 3) & 1;
    uint32_t bro[4]; uint32_t brsw[4];
#pragma unroll
    for (int p = 0; p < 4; p++) {
        int row = wn * 64 + p * 16 + lrB;
        bro[p] = 32768u + (uint32_t)row * 128;
        brsw[p] = (uint32_t)(row & 7);
    }

    float acc[2][8][4];
#pragma unroll
    for (int m2 = 0; m2 < 2; m2++)
#pragma unroll
        for (int nt = 0; nt < 8; nt++)
#pragma unroll
            for (int r = 0; r < 4; r++) acc[m2][nt][r] = 0.f;

    // ---- prologue: stage 0 (head 0) ----
    {
#pragma unroll
        for (int i = 0; i < 4; i++) {
            uint32_t chunk = (uint32_t)(bhalf * 4 + i);
            uint32_t dst = brow_off + ((chunk ^ bswz) * 16);
            cp16(sbase + dst, bhsrc + chunk * 8);
            cp16(sbase + dst + 32768u, blsrc + chunk * 8);
        }
        CP_COMMIT();
        float sc = __ldg(srow);
        float4 v0 = *(const float4*)(asrc);
        float4 v1 = *(const float4*)(asrc + 4);
        float4 v2 = *(const float4*)(asrc + 8);
        float4 v3 = *(const float4*)(asrc + 12);
        uint4 h0, l0, h1, l1;
        conv8(v0, v1, sc, h0, l0);
        conv8(v2, v3, sc, h1, l1);
        *(uint4*)(smem + ao0) = h0;
        *(uint4*)(smem + ao1) = h1;
        *(uint4*)(smem + 16384 + ao0) = l0;
        *(uint4*)(smem + 16384 + ao1) = l1;
    }

    for (int c = 0; c < 8; c++) {
        int s = c & 1;
        uint32_t stg = sbase + s * K4_STAGE;

        CP_WAIT(0);
        __syncthreads();

        // issue next stage's B cp.async immediately (overlaps with MMAs)
        if (c < 7) {
            uint32_t nst = sbase + (s ^ 1) * K4_STAGE;
#pragma unroll
            for (int i = 0; i < 4; i++) {
                uint32_t chunk = (uint32_t)(bhalf * 4 + i);
                uint32_t dst = brow_off + ((chunk ^ bswz) * 16);
                cp16(nst + dst, bhsrc + (c + 1) * 64 + chunk * 8);
                cp16(nst + dst + 32768u, blsrc + (c + 1) * 64 + chunk * 8);
            }
            CP_COMMIT();
        }

        // ---- MMA block with intra-warp fragment double buffering ----
        {
            uint32_t afh[2][2][4], afl[2][2][4];   // [buf][m2][frag]
            uint32_t bfh[2][4], bfl[2][4];         // [buf][frag]

            // preload k16=0 A frags and (k16=0,p=0) B frags
#pragma unroll
            for (int m2 = 0; m2 < 2; m2++) {
                uint32_t ao = stg + amo[m2] + (((0u + (uint32_t)lcA) ^ amsw[m2]) * 16);
                ldsm4(afh[0][m2], ao);
                ldsm4(afl[0][m2], ao + 16384u);
            }
            {
                uint32_t bof = stg + bro[0] + (((0u + (uint32_t)lcB) ^ brsw[0]) * 16);
                ldsm4(bfh[0], bof);
                ldsm4(bfl[0], bof + 32768u);
            }

#pragma unroll
            for (int k16 = 0; k16 < 4; k16++) {
                int ab = k16 & 1;
#pragma unroll
                for (int p = 0; p < 4; p++) {
                    int bb = p & 1;
                    // prefetch next fragments BEFORE current MMAs
                    if (p < 3) {
                        uint32_t bof = stg + bro[p + 1]
                                     + ((((uint32_t)(k16 * 2) + lcB) ^ brsw[p + 1]) * 16);
                        ldsm4(bfh[bb ^ 1], bof);
                        ldsm4(bfl[bb ^ 1], bof + 32768u);
                    } else if (k16 < 3) {
#pragma unroll
                        for (int m2 = 0; m2 < 2; m2++) {
                            uint32_t ao = stg + amo[m2]
                                        + ((((uint32_t)((k16 + 1) * 2) + lcA) ^ amsw[m2]) * 16);
                            ldsm4(afh[ab ^ 1][m2], ao);
                            ldsm4(afl[ab ^ 1][m2], ao + 16384u);
                        }
                        uint32_t bof = stg + bro[0]
                                     + ((((uint32_t)((k16 + 1) * 2) + lcB) ^ brsw[0]) * 16);
                        ldsm4(bfh[bb ^ 1], bof);
                        ldsm4(bfl[bb ^ 1], bof + 32768u);
                    }
                    // 12 MMAs on current fragments
#pragma unroll
                    for (int j = 0; j < 2; j++)
#pragma unroll
                        for (int m2 = 0; m2 < 2; m2++)
                            mma16816(acc[m2][p * 2 + j], afh[ab][m2], &bfh[bb][j * 2]);
#pragma unroll
                    for (int j = 0; j < 2; j++)
#pragma unroll
                        for (int m2 = 0; m2 < 2; m2++)
                            mma16816(acc[m2][p * 2 + j], afh[ab][m2], &bfl[bb][j * 2]);
#pragma unroll
                    for (int j = 0; j < 2; j++)
#pragma unroll
                        for (int m2 = 0; m2 < 2; m2++)
                            mma16816(acc[m2][p * 2 + j], afl[ab][m2], &bfh[bb][j * 2]);
                }
            }
        }

        // ---- load + convert next stage's A (after MMAs; frees prefetch regs)
        if (c < 7) {
            float psc = __ldg(srow + c + 1);
            const float* ap = asrc + (c + 1) * 64;
            float4 v0 = *(const float4*)(ap);
            float4 v1 = *(const float4*)(ap + 4);
            float4 v2 = *(const float4*)(ap + 8);
            float4 v3 = *(const float4*)(ap + 12);
            uint4 h0, l0, h1, l1;
            conv8(v0, v1, psc, h0, l0);
            conv8(v2, v3, psc, h1, l1);
            char* np = smem + (s ^ 1) * K4_STAGE;
            *(uint4*)(np + ao0) = h0;
            *(uint4*)(np + ao1) = h1;
            *(uint4*)(np + 16384 + ao0) = l0;
            *(uint4*)(np + 16384 + ao1) = l1;
        }
    }

    // epilogue: add bias, write fp32
    int r0 = lane >> 2, cbase = 2 * (lane & 3);
#pragma unroll
    for (int m2 = 0; m2 < 2; m2++) {
        size_t row = rowbase + wm * 32 + m2 * 16 + r0;
        float* orow0 = out + row * 512 + f0 + wn * 64;
        float* orow1 = orow0 + (size_t)8 * 512;
        const float* bp = bo + f0 + wn * 64;
#pragma unroll
        for (int nt = 0; nt < 8; nt++) {
            int col = nt * 8 + cbase;
            float b0v = bp[col], b1v = bp[col + 1];
            float2 v0 = make_float2(acc[m2][nt][0] + b0v, acc[m2][nt][1] + b1v);
            float2 v1 = make_float2(acc[m2][nt][2] + b0v, acc[m2][nt][3] + b1v);
            *(float2*)(orow0 + col) = v0;
            *(float2*)(orow1 + col) = v1;
        }
    }
}

// ---------------------------------------------------------------------------
extern "C" void kernel_launch(void* const* d_in, const int* in_sizes, int n_in,
                              void* d_out, int out_size) {
    const float* queries = (const float*)d_in[0];
    const float* keys    = (const float*)d_in[1];
    const float* values  = (const float*)d_in[2];
    const float* Wq      = (const float*)d_in[3];
    const float* Wk      = (const float*)d_in[4];
    const float* Wv      = (const float*)d_in[5];
    const float* Wo      = (const float*)d_in[6];
    const float* bo      = (const float*)d_in[7];
    const float* gamma   = (const float*)d_in[8];
    float* out = (float*)d_out;

    cudaFuncSetAttribute(k4_mma, cudaFuncAttributeMaxDynamicSharedMemorySize, K4_SMEM);

    k1_moment<<<CB * CH * NCH, 256>>>(keys, values);
    k2_prepG<<<CB * CH * 8, 256>>>(Wq, Wk, Wv, Wo, gamma);
    k3_mma<<<CB * CL / 64, 256>>>(queries, Wq, gamma);
    k4_mma<<<dim3(2, CL / 128, CB), 512, K4_SMEM>>>(queries, bo, out);
}